// round 2
// baseline (speedup 1.0000x reference)
#include <cuda_runtime.h>

// ---------------- problem constants ----------------
#define Bsz   16
#define Cdim  512
#define NHd   16
#define HDd   32
#define Ltok  4096            // 64*64 tokens per batch
#define Mrows 65536           // B * L  (= 1024 windows * 64 tokens)
#define HIDd  2048

// ---------------- scratch (device globals; no allocations allowed) --------
__device__ float g_xw  [(size_t)Mrows * Cdim];   // LN1 output, window order
__device__ float g_qkv [(size_t)Mrows * 3 * Cdim];
__device__ float g_attn[(size_t)Mrows * Cdim];   // attention output, window order
__device__ float g_x2  [(size_t)Mrows * Cdim];   // shortcut + proj, natural order
__device__ float g_xm  [(size_t)Mrows * Cdim];   // LN2 output
__device__ float g_h   [(size_t)Mrows * HIDd];   // fc1+gelu output

// windowed row r -> (batch, natural token l)
__device__ __forceinline__ void win_to_nat(int r, int& bt, int& l) {
    int wb = r >> 6, n = r & 63;
    bt = wb >> 6;
    int wi = wb & 63;
    int hb = wi >> 3, wk = wi & 7;
    l = (((hb << 3) + (n >> 3)) << 6) + (wk << 3) + (n & 7);
}

// ---------------- LayerNorm (one block per row, 128 threads) --------------
__global__ __launch_bounds__(128) void ln_kernel(
    const float* __restrict__ x, const float* __restrict__ g,
    const float* __restrict__ b, float* __restrict__ out, int windowed)
{
    int r = blockIdx.x;
    size_t ibase, obase;
    if (windowed) {
        int bt, l; win_to_nat(r, bt, l);
        ibase = ((size_t)bt * Ltok + l) * Cdim;
        obase = (size_t)r * Cdim;
    } else {
        ibase = obase = (size_t)r * Cdim;
    }
    int t = threadIdx.x;
    float4 v = *(const float4*)(x + ibase + t * 4);
    float s  = v.x + v.y + v.z + v.w;
    float sq = v.x*v.x + v.y*v.y + v.z*v.z + v.w*v.w;
    #pragma unroll
    for (int off = 16; off; off >>= 1) {
        s  += __shfl_xor_sync(0xffffffffu, s,  off);
        sq += __shfl_xor_sync(0xffffffffu, sq, off);
    }
    __shared__ float ws[4], wq[4];
    int wid = t >> 5, lane = t & 31;
    if (lane == 0) { ws[wid] = s; wq[wid] = sq; }
    __syncthreads();
    s  = ws[0] + ws[1] + ws[2] + ws[3];
    sq = wq[0] + wq[1] + wq[2] + wq[3];
    float mean = s * (1.0f / 512.0f);
    float var  = sq * (1.0f / 512.0f) - mean * mean;
    float rstd = rsqrtf(var + 1e-5f);
    float4 gg = *(const float4*)(g + t * 4);
    float4 bb = *(const float4*)(b + t * 4);
    float4 o;
    o.x = (v.x - mean) * rstd * gg.x + bb.x;
    o.y = (v.y - mean) * rstd * gg.y + bb.y;
    o.z = (v.z - mean) * rstd * gg.z + bb.z;
    o.w = (v.w - mean) * rstd * gg.w + bb.w;
    *(float4*)(out + obase + t * 4) = o;
}

// ---------------- SGEMM: C = A(MxK) * Bw(NxK)^T + epilogue ----------------
#define BMt 128
#define BNt 128
#define BKt 16

#define EP_BIAS 0
#define EP_GELU 1
#define EP_PROJ 2
#define EP_ADD  3

template<int EPI>
__global__ __launch_bounds__(256) void sgemm_kernel(
    int M, int N, int K,
    const float* __restrict__ A, const float* __restrict__ Bw,
    const float* __restrict__ bias, const float* __restrict__ res,
    float* __restrict__ Cc)
{
    __shared__ float As[BKt][BMt];
    __shared__ float Bs[BKt][BNt];
    const int tid = threadIdx.x;
    const int bm = blockIdx.y * BMt;
    const int bn = blockIdx.x * BNt;
    const int tm = (tid >> 4) << 3;
    const int tn = (tid & 15) << 3;

    float acc[8][8];
    #pragma unroll
    for (int i = 0; i < 8; i++)
        #pragma unroll
        for (int j = 0; j < 8; j++) acc[i][j] = 0.0f;

    const float* Aptr = A + (size_t)bm * K;
    const float* Bptr = Bw + (size_t)bn * K;

    for (int k0 = 0; k0 < K; k0 += BKt) {
        for (int v = tid; v < 512; v += 256) {
            int row = v >> 2, c4 = (v & 3) << 2;
            float4 a4 = *(const float4*)(Aptr + (size_t)row * K + k0 + c4);
            As[c4 + 0][row] = a4.x; As[c4 + 1][row] = a4.y;
            As[c4 + 2][row] = a4.z; As[c4 + 3][row] = a4.w;
            float4 b4 = *(const float4*)(Bptr + (size_t)row * K + k0 + c4);
            Bs[c4 + 0][row] = b4.x; Bs[c4 + 1][row] = b4.y;
            Bs[c4 + 2][row] = b4.z; Bs[c4 + 3][row] = b4.w;
        }
        __syncthreads();
        #pragma unroll
        for (int kk = 0; kk < BKt; kk++) {
            float ra[8], rb[8];
            *(float4*)(ra)     = *(const float4*)&As[kk][tm];
            *(float4*)(ra + 4) = *(const float4*)&As[kk][tm + 4];
            *(float4*)(rb)     = *(const float4*)&Bs[kk][tn];
            *(float4*)(rb + 4) = *(const float4*)&Bs[kk][tn + 4];
            #pragma unroll
            for (int i = 0; i < 8; i++)
                #pragma unroll
                for (int j = 0; j < 8; j++)
                    acc[i][j] += ra[i] * rb[j];
        }
        __syncthreads();
    }

    #pragma unroll
    for (int i = 0; i < 8; i++) {
        int row = bm + tm + i;
        size_t obase;
        if (EPI == EP_PROJ) {
            int bt, l; win_to_nat(row, bt, l);
            obase = ((size_t)bt * Ltok + l) * (size_t)N;
        } else {
            obase = (size_t)row * (size_t)N;
        }
        #pragma unroll
        for (int j = 0; j < 8; j += 4) {
            float4 o;
            float* ov = (float*)&o;
            #pragma unroll
            for (int u = 0; u < 4; u++) {
                int col = bn + tn + j + u;
                float v = acc[i][j + u] + bias[col];
                if (EPI == EP_GELU) {
                    v = 0.5f * v * (1.0f + erff(v * 0.70710678118654752f));
                } else if (EPI == EP_PROJ || EPI == EP_ADD) {
                    v += res[obase + col];
                }
                ov[u] = v;
            }
            *(float4*)(Cc + obase + bn + tn + j) = o;
        }
    }
}

// ---------------- fused windowed attention (one block per window*head) ----
#define QSCALE 0.17677669529663687f   // 1/sqrt(32)
#define AZC    0.09817477042468103f   // 2*pi/64
#define RDC    0.02454369260617026f   // 2*pi/256

__global__ __launch_bounds__(256) void attn_kernel(
    const float* __restrict__ qkv, const float* __restrict__ Dp,
    const float* __restrict__ a_p, const float* __restrict__ b_p,
    const float* __restrict__ a_r, const float* __restrict__ b_r,
    float* __restrict__ outp)
{
    __shared__ float QK[4224];          // Qs[64][33] + Ks[64][33]; later Ss[64][65]
    __shared__ float Vs[64][33];
    __shared__ float csr[15][64];
    __shared__ float ssr[15][64];
    __shared__ float arh[15], brh[15], phs[15];

    const int wb  = blockIdx.x;   // 0..1023
    const int h   = blockIdx.y;   // 0..15
    const int tid = threadIdx.x;  // 256
    float* Qs = QK;
    float* Ks = QK + 64 * 33;

    // load Q,K,V (scaled Q) into padded smem
    for (int v = tid; v < 512; v += 256) {
        int n = v >> 3, d4 = (v & 7) << 2;
        size_t base = ((size_t)(wb * 64 + n)) * 1536 + h * 32 + d4;
        float4 q4 = *(const float4*)(qkv + base);
        Qs[n * 33 + d4 + 0] = q4.x * QSCALE;
        Qs[n * 33 + d4 + 1] = q4.y * QSCALE;
        Qs[n * 33 + d4 + 2] = q4.z * QSCALE;
        Qs[n * 33 + d4 + 3] = q4.w * QSCALE;
        float4 k4 = *(const float4*)(qkv + base + 512);
        Ks[n * 33 + d4 + 0] = k4.x; Ks[n * 33 + d4 + 1] = k4.y;
        Ks[n * 33 + d4 + 2] = k4.z; Ks[n * 33 + d4 + 3] = k4.w;
        float4 v4 = *(const float4*)(qkv + base + 1024);
        Vs[n][d4 + 0] = v4.x; Vs[n][d4 + 1] = v4.y;
        Vs[n][d4 + 2] = v4.z; Vs[n][d4 + 3] = v4.w;
    }
    // per-window radial cos/sin tables: ang = dy * D[b,j] * 2pi/256
    {
        int bt = wb >> 6, wi = wb & 63, hb = wi >> 3, wk = wi & 7;
        for (int v = tid; v < 960; v += 256) {
            int dyp = v >> 6, jj = v & 63;
            float Dv = Dp[bt * 4096 + (((hb << 3) + (jj >> 3)) << 6) + (wk << 3) + (jj & 7)];
            float ang = (float)(dyp - 7) * Dv * RDC;
            float sn, cs; __sincosf(ang, &sn, &cs);
            csr[dyp][jj] = cs; ssr[dyp][jj] = sn;
        }
    }
    // per-head azimuth bias (depends only on dx) + radial table columns
    if (tid < 15) {
        arh[tid] = a_r[tid * NHd + h];
        brh[tid] = b_r[tid * NHd + h];
        int dx = tid - 7;
        int ip = dx < 0 ? dx + 15 : dx;
        float azf = (float)dx * AZC;
        float sn, cs; __sincosf(azf, &sn, &cs);
        phs[tid] = a_p[ip * NHd + h] * cs + b_p[ip * NHd + h] * sn;
    }
    __syncthreads();

    // S = Q K^T + biases : thread (ig, j) computes rows ig*16..+15, column j
    const int j = tid & 63, ig = tid >> 6;
    float acc[16];
    #pragma unroll
    for (int ii = 0; ii < 16; ii++) acc[ii] = 0.0f;
    #pragma unroll 8
    for (int d = 0; d < 32; d++) {
        float kv = Ks[j * 33 + d];
        #pragma unroll
        for (int ii = 0; ii < 16; ii++)
            acc[ii] += Qs[(ig * 16 + ii) * 33 + d] * kv;
    }
    const int yj = j >> 3, xjm = j & 7;
    #pragma unroll
    for (int ii = 0; ii < 16; ii++) {
        int i = ig * 16 + ii;
        int dy = (i >> 3) - yj;
        int dyp = dy + 7;
        int ir = dy < 0 ? dy + 15 : dy;
        int dxp = (i & 7) - xjm + 7;
        acc[ii] += phs[dxp] + arh[ir] * csr[dyp][j] + brh[ir] * ssr[dyp][j];
    }
    __syncthreads();                 // done reading Qs/Ks
    float* Ss = QK;                  // [64][65]
    #pragma unroll
    for (int ii = 0; ii < 16; ii++) Ss[(ig * 16 + ii) * 65 + j] = acc[ii];
    __syncthreads();

    // softmax per row: thread t -> row t>>2, quarter t&3 (16 cols each)
    {
        int i = tid >> 2, p = tid & 3;
        float vals[16];
        float mx = -1e30f;
        #pragma unroll
        for (int u = 0; u < 16; u++) { vals[u] = Ss[i * 65 + p * 16 + u]; mx = fmaxf(mx, vals[u]); }
        mx = fmaxf(mx, __shfl_xor_sync(0xffffffffu, mx, 1));
        mx = fmaxf(mx, __shfl_xor_sync(0xffffffffu, mx, 2));
        float sm = 0.0f;
        #pragma unroll
        for (int u = 0; u < 16; u++) { vals[u] = __expf(vals[u] - mx); sm += vals[u]; }
        sm += __shfl_xor_sync(0xffffffffu, sm, 1);
        sm += __shfl_xor_sync(0xffffffffu, sm, 2);
        float inv = 1.0f / sm;
        #pragma unroll
        for (int u = 0; u < 16; u++) Ss[i * 65 + p * 16 + u] = vals[u] * inv;
    }
    __syncthreads();

    // O = P V : thread (ig2, d) computes rows ig2*8..+7, dim d
    {
        int d = tid & 31, ig2 = tid >> 5;
        float acc2[8];
        #pragma unroll
        for (int u = 0; u < 8; u++) acc2[u] = 0.0f;
        #pragma unroll 4
        for (int m = 0; m < 64; m++) {
            float vv = Vs[m][d];
            #pragma unroll
            for (int u = 0; u < 8; u++)
                acc2[u] += Ss[(ig2 * 8 + u) * 65 + m] * vv;
        }
        #pragma unroll
        for (int u = 0; u < 8; u++) {
            int i = ig2 * 8 + u;
            outp[((size_t)(wb * 64 + i)) * Cdim + h * HDd + d] = acc2[u];
        }
    }
}

// ---------------- launch -------------------------------------------------
extern "C" void kernel_launch(void* const* d_in, const int* in_sizes, int n_in,
                              void* d_out, int out_size) {
    (void)in_sizes; (void)n_in; (void)out_size;
    const float* x      = (const float*)d_in[0];
    const float* D      = (const float*)d_in[1];
    const float* n1g    = (const float*)d_in[2];
    const float* n1b    = (const float*)d_in[3];
    const float* qkv_w  = (const float*)d_in[4];
    const float* qkv_b  = (const float*)d_in[5];
    const float* proj_w = (const float*)d_in[6];
    const float* proj_b = (const float*)d_in[7];
    const float* a_p    = (const float*)d_in[8];
    const float* b_p    = (const float*)d_in[9];
    const float* a_r    = (const float*)d_in[10];
    const float* b_r    = (const float*)d_in[11];
    const float* n2g    = (const float*)d_in[12];
    const float* n2b    = (const float*)d_in[13];
    const float* fc1_w  = (const float*)d_in[14];
    const float* fc1_b  = (const float*)d_in[15];
    const float* fc2_w  = (const float*)d_in[16];
    const float* fc2_b  = (const float*)d_in[17];
    float* out = (float*)d_out;

    float *xw, *qkvb, *attnb, *x2, *xm, *hb;
    cudaGetSymbolAddress((void**)&xw,    g_xw);
    cudaGetSymbolAddress((void**)&qkvb,  g_qkv);
    cudaGetSymbolAddress((void**)&attnb, g_attn);
    cudaGetSymbolAddress((void**)&x2,    g_x2);
    cudaGetSymbolAddress((void**)&xm,    g_xm);
    cudaGetSymbolAddress((void**)&hb,    g_h);

    // 1) LN1 + window partition
    ln_kernel<<<Mrows, 128>>>(x, n1g, n1b, xw, 1);
    // 2) QKV GEMM: (65536,512) x (1536,512)^T
    sgemm_kernel<EP_BIAS><<<dim3(1536 / BNt, Mrows / BMt), 256>>>(
        Mrows, 1536, Cdim, xw, qkv_w, qkv_b, nullptr, qkvb);
    // 3) fused windowed attention
    attn_kernel<<<dim3(1024, 16), 256>>>(qkvb, D, a_p, b_p, a_r, b_r, attnb);
    // 4) proj GEMM + window reverse + residual -> x2 (natural order)
    sgemm_kernel<EP_PROJ><<<dim3(Cdim / BNt, Mrows / BMt), 256>>>(
        Mrows, Cdim, Cdim, attnb, proj_w, proj_b, x, x2);
    // 5) LN2
    ln_kernel<<<Mrows, 128>>>(x2, n2g, n2b, xm, 0);
    // 6) fc1 + exact GELU
    sgemm_kernel<EP_GELU><<<dim3(HIDd / BNt, Mrows / BMt), 256>>>(
        Mrows, HIDd, Cdim, xm, fc1_w, fc1_b, nullptr, hb);
    // 7) fc2 + residual -> output
    sgemm_kernel<EP_ADD><<<dim3(Cdim / BNt, Mrows / BMt), 256>>>(
        Mrows, Cdim, HIDd, hb, fc2_w, fc2_b, x2, out);
}

// round 5
// speedup vs baseline: 2.3899x; 2.3899x over previous
#include <cuda_runtime.h>
#include <cuda_bf16.h>
#include <cstdint>

// ---------------- problem constants ----------------
#define Cdim  512
#define NHd   16
#define HDd   32
#define Ltok  4096
#define Mrows 65536
#define HIDd  2048

// ---------------- scratch (device globals) --------------------------------
__device__ __nv_bfloat16 g_xw_h[(size_t)Mrows * Cdim];
__device__ __nv_bfloat16 g_xw_l[(size_t)Mrows * Cdim];
__device__ float         g_qkv [(size_t)Mrows * 3 * Cdim];
__device__ __nv_bfloat16 g_at_h[(size_t)Mrows * Cdim];
__device__ __nv_bfloat16 g_at_l[(size_t)Mrows * Cdim];
__device__ float         g_x2  [(size_t)Mrows * Cdim];
__device__ __nv_bfloat16 g_xm_h[(size_t)Mrows * Cdim];
__device__ __nv_bfloat16 g_xm_l[(size_t)Mrows * Cdim];
__device__ __nv_bfloat16 g_h_h [(size_t)Mrows * HIDd];
__device__ __nv_bfloat16 g_h_l [(size_t)Mrows * HIDd];
__device__ __nv_bfloat16 g_wq_h[1536 * 512], g_wq_l[1536 * 512];
__device__ __nv_bfloat16 g_wp_h[512 * 512],  g_wp_l[512 * 512];
__device__ __nv_bfloat16 g_w1_h[2048 * 512], g_w1_l[2048 * 512];
__device__ __nv_bfloat16 g_w2_h[512 * 2048], g_w2_l[512 * 2048];

// windowed row r -> (batch, natural token l)
__device__ __forceinline__ void win_to_nat(int r, int& bt, int& l) {
    int wb = r >> 6, n = r & 63;
    bt = wb >> 6;
    int wi = wb & 63;
    int hb = wi >> 3, wk = wi & 7;
    l = (((hb << 3) + (n >> 3)) << 6) + (wk << 3) + (n & 7);
}

// ---------------- PTX helpers ---------------------------------------------
__device__ __forceinline__ uint32_t smem_u32(const void* p) {
    uint32_t a;
    asm("{ .reg .u64 t; cvta.to.shared.u64 t, %1; cvt.u32.u64 %0, t; }" : "=r"(a) : "l"(p));
    return a;
}
__device__ __forceinline__ void cpa16(uint32_t dst, const void* src) {
    asm volatile("cp.async.cg.shared.global [%0], [%1], 16;" :: "r"(dst), "l"(src));
}
#define CP_COMMIT() asm volatile("cp.async.commit_group;" ::: "memory")
#define CP_WAIT1()  asm volatile("cp.async.wait_group 1;" ::: "memory")

// swizzle: 128B physical lines (2 logical 64B rows), XOR 16B-chunk with line idx
__device__ __forceinline__ uint32_t swz(uint32_t off) {
    return off ^ (((off >> 7) & 7) << 4);
}

__device__ __forceinline__ void ldmx4(uint32_t addr, uint32_t& r0, uint32_t& r1,
                                      uint32_t& r2, uint32_t& r3) {
    asm volatile("ldmatrix.sync.aligned.m8n8.x4.shared.b16 {%0,%1,%2,%3}, [%4];"
                 : "=r"(r0), "=r"(r1), "=r"(r2), "=r"(r3) : "r"(addr));
}
__device__ __forceinline__ void mma16816(float* c, const uint32_t* a, const uint32_t* b) {
    asm volatile(
        "mma.sync.aligned.m16n8k16.row.col.f32.bf16.bf16.f32 "
        "{%0,%1,%2,%3}, {%4,%5,%6,%7}, {%8,%9}, {%0,%1,%2,%3};"
        : "+f"(c[0]), "+f"(c[1]), "+f"(c[2]), "+f"(c[3])
        : "r"(a[0]), "r"(a[1]), "r"(a[2]), "r"(a[3]), "r"(b[0]), "r"(b[1]));
}

// ---------------- mma.sync GEMM -------------------------------------------
// C[M x Nout] = Act[M x K] * W[Nout x K]^T, bf16 hi/lo 3-pass, fp32 regs acc.
// CTA: 128 act rows x 256 out cols, K-tile 32, 8 warps (2M x 4N), warp 64x64.
#define STG   49152                 // Ah 8K | Al 8K | Wh 16K | Wl 16K
#define SMEM_TOT (3 * STG)

#define EP_BIAS 0
#define EP_GELU 1
#define EP_PROJ 2
#define EP_ADD  3

__device__ __forceinline__ void load_stage(
    uint32_t sb, int tid, int k0, int K, int bm0, int bn0,
    const __nv_bfloat16* __restrict__ Ah, const __nv_bfloat16* __restrict__ Al,
    const __nv_bfloat16* __restrict__ Wh, const __nv_bfloat16* __restrict__ Wl)
{
    #pragma unroll
    for (int i = 0; i < 2; i++) {               // Ah: 128 rows x 4 chunks
        int c = tid + i * 256, r = c >> 2, ch = c & 3;
        cpa16(sb + swz(r * 64 + ch * 16), Ah + (size_t)(bm0 + r) * K + k0 + ch * 8);
    }
    #pragma unroll
    for (int i = 0; i < 2; i++) {               // Al
        int c = tid + i * 256, r = c >> 2, ch = c & 3;
        cpa16(sb + 8192 + swz(r * 64 + ch * 16), Al + (size_t)(bm0 + r) * K + k0 + ch * 8);
    }
    #pragma unroll
    for (int i = 0; i < 4; i++) {               // Wh: 256 rows x 4 chunks
        int c = tid + i * 256, r = c >> 2, ch = c & 3;
        cpa16(sb + 16384 + swz(r * 64 + ch * 16), Wh + (size_t)(bn0 + r) * K + k0 + ch * 8);
    }
    #pragma unroll
    for (int i = 0; i < 4; i++) {               // Wl
        int c = tid + i * 256, r = c >> 2, ch = c & 3;
        cpa16(sb + 32768 + swz(r * 64 + ch * 16), Wl + (size_t)(bn0 + r) * K + k0 + ch * 8);
    }
}

template<int EPI>
__global__ void __launch_bounds__(256, 1) tgemm(
    int K, int Nout,
    const __nv_bfloat16* __restrict__ Ah, const __nv_bfloat16* __restrict__ Al,
    const __nv_bfloat16* __restrict__ Wh, const __nv_bfloat16* __restrict__ Wl,
    const float* __restrict__ bias, const float* __restrict__ res,
    float* __restrict__ outf,
    __nv_bfloat16* __restrict__ outh, __nv_bfloat16* __restrict__ outl)
{
    extern __shared__ __align__(1024) char smem[];
    const uint32_t sbase = smem_u32(smem);
    const int tid  = threadIdx.x;
    const int bn0  = blockIdx.x * 256;
    const int bm0  = blockIdx.y * 128;
    const int warp = tid >> 5, lane = tid & 31;
    const int wm = (warp >> 2) * 64;      // 0 or 64
    const int wn = (warp & 3) * 64;       // 0,64,128,192

    float acc[4][8][4];
    #pragma unroll
    for (int mf = 0; mf < 4; mf++)
        #pragma unroll
        for (int nf = 0; nf < 8; nf++)
            #pragma unroll
            for (int u = 0; u < 4; u++) acc[mf][nf][u] = 0.0f;

    const int nk = K >> 5;
    load_stage(sbase,       tid, 0,  K, bm0, bn0, Ah, Al, Wh, Wl); CP_COMMIT();
    load_stage(sbase + STG, tid, 32, K, bm0, bn0, Ah, Al, Wh, Wl); CP_COMMIT();

    const int rA = wm + (lane & 15);
    const int rB = wn + (lane & 15);
    const int cb = lane >> 4;

    for (int kt = 0; kt < nk; kt++) {
        CP_WAIT1();
        __syncthreads();
        int kn = kt + 2;
        if (kn < nk)
            load_stage(sbase + (kn % 3) * STG, tid, kn * 32, K, bm0, bn0, Ah, Al, Wh, Wl);
        CP_COMMIT();

        const uint32_t sg = sbase + (kt % 3) * STG;
        const uint32_t aT[2] = { sg, sg + 8192 };           // act hi, lo
        const uint32_t wT[2] = { sg + 16384, sg + 32768 };  // w hi, lo
        #pragma unroll
        for (int p = 0; p < 3; p++) {
            const uint32_t at = aT[p == 1];
            const uint32_t wt = wT[p == 2];
            #pragma unroll
            for (int kf = 0; kf < 2; kf++) {
                const int ch = kf * 2 + cb;
                uint32_t a[4][4];
                #pragma unroll
                for (int mf = 0; mf < 4; mf++)
                    ldmx4(at + swz((rA + mf * 16) * 64 + ch * 16),
                          a[mf][0], a[mf][1], a[mf][2], a[mf][3]);
                uint32_t b[8][2];
                #pragma unroll
                for (int n2 = 0; n2 < 4; n2++) {
                    uint32_t r0, r1, r2, r3;
                    ldmx4(wt + swz((rB + n2 * 16) * 64 + ch * 16), r0, r1, r2, r3);
                    b[2 * n2][0] = r0; b[2 * n2][1] = r2;
                    b[2 * n2 + 1][0] = r1; b[2 * n2 + 1][1] = r3;
                }
                #pragma unroll
                for (int mf = 0; mf < 4; mf++)
                    #pragma unroll
                    for (int nf = 0; nf < 8; nf++)
                        mma16816(acc[mf][nf], a[mf], b[nf]);
            }
        }
    }

    // ---------------- epilogue ----------------
    const int g = lane >> 2, q = lane & 3;
    #pragma unroll
    for (int mf = 0; mf < 4; mf++) {
        const int row0 = bm0 + wm + mf * 16 + g;
        const int row1 = row0 + 8;
        size_t ob0, ob1;
        if (EPI == EP_PROJ) {
            int bt, l;
            win_to_nat(row0, bt, l); ob0 = ((size_t)bt * Ltok + l) * (size_t)Nout;
            win_to_nat(row1, bt, l); ob1 = ((size_t)bt * Ltok + l) * (size_t)Nout;
        } else {
            ob0 = (size_t)row0 * Nout;
            ob1 = (size_t)row1 * Nout;
        }
        #pragma unroll
        for (int nf = 0; nf < 8; nf++) {
            const int col = bn0 + wn + nf * 8 + q * 2;
            const float b0 = bias[col], b1 = bias[col + 1];
            float v00 = acc[mf][nf][0] + b0, v01 = acc[mf][nf][1] + b1;
            float v10 = acc[mf][nf][2] + b0, v11 = acc[mf][nf][3] + b1;
            if (EPI == EP_BIAS) {
                *(float2*)(outf + ob0 + col) = make_float2(v00, v01);
                *(float2*)(outf + ob1 + col) = make_float2(v10, v11);
            } else if (EPI == EP_GELU) {
                v00 = 0.5f * v00 * (1.0f + erff(v00 * 0.70710678118654752f));
                v01 = 0.5f * v01 * (1.0f + erff(v01 * 0.70710678118654752f));
                v10 = 0.5f * v10 * (1.0f + erff(v10 * 0.70710678118654752f));
                v11 = 0.5f * v11 * (1.0f + erff(v11 * 0.70710678118654752f));
                __nv_bfloat16 h00 = __float2bfloat16_rn(v00), h01 = __float2bfloat16_rn(v01);
                __nv_bfloat16 h10 = __float2bfloat16_rn(v10), h11 = __float2bfloat16_rn(v11);
                *(__nv_bfloat162*)(outh + ob0 + col) = __nv_bfloat162(h00, h01);
                *(__nv_bfloat162*)(outh + ob1 + col) = __nv_bfloat162(h10, h11);
                *(__nv_bfloat162*)(outl + ob0 + col) = __nv_bfloat162(
                    __float2bfloat16_rn(v00 - __bfloat162float(h00)),
                    __float2bfloat16_rn(v01 - __bfloat162float(h01)));
                *(__nv_bfloat162*)(outl + ob1 + col) = __nv_bfloat162(
                    __float2bfloat16_rn(v10 - __bfloat162float(h10)),
                    __float2bfloat16_rn(v11 - __bfloat162float(h11)));
            } else {  // EP_PROJ / EP_ADD: += residual
                float2 r0 = *(const float2*)(res + ob0 + col);
                float2 r1 = *(const float2*)(res + ob1 + col);
                *(float2*)(outf + ob0 + col) = make_float2(v00 + r0.x, v01 + r0.y);
                *(float2*)(outf + ob1 + col) = make_float2(v10 + r1.x, v11 + r1.y);
            }
        }
    }
}

// ---------------- fp32 -> bf16 hi/lo conversion (weights) ----------------
__global__ __launch_bounds__(256) void cvt_pair(
    const float* __restrict__ src, __nv_bfloat16* __restrict__ hi,
    __nv_bfloat16* __restrict__ lo, int n)
{
    int i = blockIdx.x * 256 + threadIdx.x;
    if (i < n) {
        float v = src[i];
        __nv_bfloat16 h = __float2bfloat16_rn(v);
        hi[i] = h;
        lo[i] = __float2bfloat16_rn(v - __bfloat162float(h));
    }
}

// ---------------- LayerNorm -> bf16 hi/lo pair ----------------------------
__global__ __launch_bounds__(128) void ln_kernel(
    const float* __restrict__ x, const float* __restrict__ g,
    const float* __restrict__ b, __nv_bfloat16* __restrict__ outh,
    __nv_bfloat16* __restrict__ outl, int windowed)
{
    int r = blockIdx.x;
    size_t ibase, obase;
    if (windowed) {
        int bt, l; win_to_nat(r, bt, l);
        ibase = ((size_t)bt * Ltok + l) * Cdim;
        obase = (size_t)r * Cdim;
    } else {
        ibase = obase = (size_t)r * Cdim;
    }
    int t = threadIdx.x;
    float4 v = *(const float4*)(x + ibase + t * 4);
    float s  = v.x + v.y + v.z + v.w;
    float sq = v.x*v.x + v.y*v.y + v.z*v.z + v.w*v.w;
    #pragma unroll
    for (int off = 16; off; off >>= 1) {
        s  += __shfl_xor_sync(0xffffffffu, s,  off);
        sq += __shfl_xor_sync(0xffffffffu, sq, off);
    }
    __shared__ float ws[4], wq[4];
    int wid = t >> 5, lane = t & 31;
    if (lane == 0) { ws[wid] = s; wq[wid] = sq; }
    __syncthreads();
    s  = ws[0] + ws[1] + ws[2] + ws[3];
    sq = wq[0] + wq[1] + wq[2] + wq[3];
    float mean = s * (1.0f / 512.0f);
    float var  = sq * (1.0f / 512.0f) - mean * mean;
    float rstd = rsqrtf(var + 1e-5f);
    float4 gg = *(const float4*)(g + t * 4);
    float4 bb = *(const float4*)(b + t * 4);
    float ov[4];
    ov[0] = (v.x - mean) * rstd * gg.x + bb.x;
    ov[1] = (v.y - mean) * rstd * gg.y + bb.y;
    ov[2] = (v.z - mean) * rstd * gg.z + bb.z;
    ov[3] = (v.w - mean) * rstd * gg.w + bb.w;
    __nv_bfloat16 hv[4], lv[4];
    #pragma unroll
    for (int u = 0; u < 4; u++) {
        hv[u] = __float2bfloat16_rn(ov[u]);
        lv[u] = __float2bfloat16_rn(ov[u] - __bfloat162float(hv[u]));
    }
    *(uint2*)(outh + obase + t * 4) = *(uint2*)hv;
    *(uint2*)(outl + obase + t * 4) = *(uint2*)lv;
}

// ---------------- fused windowed attention --------------------------------
#define QSCALE 0.17677669529663687f
#define AZC    0.09817477042468103f
#define RDC    0.02454369260617026f

__global__ __launch_bounds__(256) void attn_kernel(
    const float* __restrict__ qkv, const float* __restrict__ Dp,
    const float* __restrict__ a_p, const float* __restrict__ b_p,
    const float* __restrict__ a_r, const float* __restrict__ b_r,
    __nv_bfloat16* __restrict__ outh, __nv_bfloat16* __restrict__ outl)
{
    __shared__ float QK[4224];
    __shared__ float Vs[64][33];
    __shared__ float csr[15][64];
    __shared__ float ssr[15][64];
    __shared__ float arh[15], brh[15], phs[15];

    const int wb  = blockIdx.x;
    const int h   = blockIdx.y;
    const int tid = threadIdx.x;
    float* Qs = QK;
    float* Ks = QK + 64 * 33;

    for (int v = tid; v < 512; v += 256) {
        int n = v >> 3, d4 = (v & 7) << 2;
        size_t base = ((size_t)(wb * 64 + n)) * 1536 + h * 32 + d4;
        float4 q4 = *(const float4*)(qkv + base);
        Qs[n * 33 + d4 + 0] = q4.x * QSCALE;
        Qs[n * 33 + d4 + 1] = q4.y * QSCALE;
        Qs[n * 33 + d4 + 2] = q4.z * QSCALE;
        Qs[n * 33 + d4 + 3] = q4.w * QSCALE;
        float4 k4 = *(const float4*)(qkv + base + 512);
        Ks[n * 33 + d4 + 0] = k4.x; Ks[n * 33 + d4 + 1] = k4.y;
        Ks[n * 33 + d4 + 2] = k4.z; Ks[n * 33 + d4 + 3] = k4.w;
        float4 v4 = *(const float4*)(qkv + base + 1024);
        Vs[n][d4 + 0] = v4.x; Vs[n][d4 + 1] = v4.y;
        Vs[n][d4 + 2] = v4.z; Vs[n][d4 + 3] = v4.w;
    }
    {
        int bt = wb >> 6, wi = wb & 63, hb = wi >> 3, wk = wi & 7;
        for (int v = tid; v < 960; v += 256) {
            int dyp = v >> 6, jj = v & 63;
            float Dv = Dp[bt * 4096 + (((hb << 3) + (jj >> 3)) << 6) + (wk << 3) + (jj & 7)];
            float ang = (float)(dyp - 7) * Dv * RDC;
            float sn, cs; __sincosf(ang, &sn, &cs);
            csr[dyp][jj] = cs; ssr[dyp][jj] = sn;
        }
    }
    if (tid < 15) {
        arh[tid] = a_r[tid * NHd + h];
        brh[tid] = b_r[tid * NHd + h];
        int dx = tid - 7;
        int ip = dx < 0 ? dx + 15 : dx;
        float azf = (float)dx * AZC;
        float sn, cs; __sincosf(azf, &sn, &cs);
        phs[tid] = a_p[ip * NHd + h] * cs + b_p[ip * NHd + h] * sn;
    }
    __syncthreads();

    const int j = tid & 63, ig = tid >> 6;
    float acc[16];
    #pragma unroll
    for (int ii = 0; ii < 16; ii++) acc[ii] = 0.0f;
    #pragma unroll 8
    for (int d = 0; d < 32; d++) {
        float kv = Ks[j * 33 + d];
        #pragma unroll
        for (int ii = 0; ii < 16; ii++)
            acc[ii] += Qs[(ig * 16 + ii) * 33 + d] * kv;
    }
    const int yj = j >> 3, xjm = j & 7;
    #pragma unroll
    for (int ii = 0; ii < 16; ii++) {
        int i = ig * 16 + ii;
        int dy = (i >> 3) - yj;
        int dyp = dy + 7;
        int ir = dy < 0 ? dy + 15 : dy;
        int dxp = (i & 7) - xjm + 7;
        acc[ii] += phs[dxp] + arh[ir] * csr[dyp][j] + brh[ir] * ssr[dyp][j];
    }
    __syncthreads();
    float* Ss = QK;
    #pragma unroll
    for (int ii = 0; ii < 16; ii++) Ss[(ig * 16 + ii) * 65 + j] = acc[ii];
    __syncthreads();

    {
        int i = tid >> 2, p = tid & 3;
        float vals[16];
        float mx = -1e30f;
        #pragma unroll
        for (int u = 0; u < 16; u++) { vals[u] = Ss[i * 65 + p * 16 + u]; mx = fmaxf(mx, vals[u]); }
        mx = fmaxf(mx, __shfl_xor_sync(0xffffffffu, mx, 1));
        mx = fmaxf(mx, __shfl_xor_sync(0xffffffffu, mx, 2));
        float sm = 0.0f;
        #pragma unroll
        for (int u = 0; u < 16; u++) { vals[u] = __expf(vals[u] - mx); sm += vals[u]; }
        sm += __shfl_xor_sync(0xffffffffu, sm, 1);
        sm += __shfl_xor_sync(0xffffffffu, sm, 2);
        float inv = 1.0f / sm;
        #pragma unroll
        for (int u = 0; u < 16; u++) Ss[i * 65 + p * 16 + u] = vals[u] * inv;
    }
    __syncthreads();

    {
        int d = tid & 31, ig2 = tid >> 5;
        float acc2[8];
        #pragma unroll
        for (int u = 0; u < 8; u++) acc2[u] = 0.0f;
        #pragma unroll 4
        for (int m = 0; m < 64; m++) {
            float vv = Vs[m][d];
            #pragma unroll
            for (int u = 0; u < 8; u++)
                acc2[u] += Ss[(ig2 * 8 + u) * 65 + m] * vv;
        }
        #pragma unroll
        for (int u = 0; u < 8; u++) {
            int i = ig2 * 8 + u;
            size_t o = ((size_t)(wb * 64 + i)) * Cdim + h * HDd + d;
            float v = acc2[u];
            __nv_bfloat16 hh = __float2bfloat16_rn(v);
            outh[o] = hh;
            outl[o] = __float2bfloat16_rn(v - __bfloat162float(hh));
        }
    }
}

// ---------------- launch -------------------------------------------------
extern "C" void kernel_launch(void* const* d_in, const int* in_sizes, int n_in,
                              void* d_out, int out_size) {
    (void)in_sizes; (void)n_in; (void)out_size;
    const float* x      = (const float*)d_in[0];
    const float* D      = (const float*)d_in[1];
    const float* n1g    = (const float*)d_in[2];
    const float* n1b    = (const float*)d_in[3];
    const float* qkv_w  = (const float*)d_in[4];
    const float* qkv_b  = (const float*)d_in[5];
    const float* proj_w = (const float*)d_in[6];
    const float* proj_b = (const float*)d_in[7];
    const float* a_p    = (const float*)d_in[8];
    const float* b_p    = (const float*)d_in[9];
    const float* a_r    = (const float*)d_in[10];
    const float* b_r    = (const float*)d_in[11];
    const float* n2g    = (const float*)d_in[12];
    const float* n2b    = (const float*)d_in[13];
    const float* fc1_w  = (const float*)d_in[14];
    const float* fc1_b  = (const float*)d_in[15];
    const float* fc2_w  = (const float*)d_in[16];
    const float* fc2_b  = (const float*)d_in[17];
    float* out = (float*)d_out;

    __nv_bfloat16 *xwh, *xwl, *ath, *atl, *xmh, *xml, *hh, *hl;
    __nv_bfloat16 *wqh, *wql, *wph, *wpl, *w1h, *w1l, *w2h, *w2l;
    float *qkvb, *x2;
    cudaGetSymbolAddress((void**)&xwh, g_xw_h); cudaGetSymbolAddress((void**)&xwl, g_xw_l);
    cudaGetSymbolAddress((void**)&ath, g_at_h); cudaGetSymbolAddress((void**)&atl, g_at_l);
    cudaGetSymbolAddress((void**)&xmh, g_xm_h); cudaGetSymbolAddress((void**)&xml, g_xm_l);
    cudaGetSymbolAddress((void**)&hh,  g_h_h);  cudaGetSymbolAddress((void**)&hl,  g_h_l);
    cudaGetSymbolAddress((void**)&wqh, g_wq_h); cudaGetSymbolAddress((void**)&wql, g_wq_l);
    cudaGetSymbolAddress((void**)&wph, g_wp_h); cudaGetSymbolAddress((void**)&wpl, g_wp_l);
    cudaGetSymbolAddress((void**)&w1h, g_w1_h); cudaGetSymbolAddress((void**)&w1l, g_w1_l);
    cudaGetSymbolAddress((void**)&w2h, g_w2_h); cudaGetSymbolAddress((void**)&w2l, g_w2_l);
    cudaGetSymbolAddress((void**)&qkvb, g_qkv); cudaGetSymbolAddress((void**)&x2, g_x2);

    cudaFuncSetAttribute(tgemm<EP_BIAS>, cudaFuncAttributeMaxDynamicSharedMemorySize, SMEM_TOT);
    cudaFuncSetAttribute(tgemm<EP_GELU>, cudaFuncAttributeMaxDynamicSharedMemorySize, SMEM_TOT);
    cudaFuncSetAttribute(tgemm<EP_PROJ>, cudaFuncAttributeMaxDynamicSharedMemorySize, SMEM_TOT);
    cudaFuncSetAttribute(tgemm<EP_ADD>,  cudaFuncAttributeMaxDynamicSharedMemorySize, SMEM_TOT);

    // weight conversions
    cvt_pair<<<(1536 * 512) / 256, 256>>>(qkv_w,  wqh, wql, 1536 * 512);
    cvt_pair<<<(512 * 512)  / 256, 256>>>(proj_w, wph, wpl, 512 * 512);
    cvt_pair<<<(2048 * 512) / 256, 256>>>(fc1_w,  w1h, w1l, 2048 * 512);
    cvt_pair<<<(512 * 2048) / 256, 256>>>(fc2_w,  w2h, w2l, 512 * 2048);

    // 1) LN1 + window partition -> bf16 pair
    ln_kernel<<<Mrows, 128>>>(x, n1g, n1b, xwh, xwl, 1);
    // 2) QKV GEMM
    tgemm<EP_BIAS><<<dim3(1536 / 256, Mrows / 128), 256, SMEM_TOT>>>(
        512, 1536, xwh, xwl, wqh, wql, qkv_b, nullptr, qkvb, nullptr, nullptr);
    // 3) fused windowed attention -> bf16 pair
    attn_kernel<<<dim3(1024, 16), 256>>>(qkvb, D, a_p, b_p, a_r, b_r, ath, atl);
    // 4) proj GEMM + window reverse + residual
    tgemm<EP_PROJ><<<dim3(512 / 256, Mrows / 128), 256, SMEM_TOT>>>(
        512, 512, ath, atl, wph, wpl, proj_b, x, x2, nullptr, nullptr);
    // 5) LN2 -> bf16 pair
    ln_kernel<<<Mrows, 128>>>(x2, n2g, n2b, xmh, xml, 0);
    // 6) fc1 + GELU -> bf16 pair
    tgemm<EP_GELU><<<dim3(2048 / 256, Mrows / 128), 256, SMEM_TOT>>>(
        512, 2048, xmh, xml, w1h, w1l, fc1_b, nullptr, nullptr, hh, hl);
    // 7) fc2 + residual -> output
    tgemm<EP_ADD><<<dim3(512 / 256, Mrows / 128), 256, SMEM_TOT>>>(
        2048, 512, hh, hl, w2h, w2l, fc2_b, x2, out, nullptr, nullptr);
}

// round 8
// speedup vs baseline: 2.7768x; 1.1619x over previous
#include <cuda_runtime.h>
#include <cuda_bf16.h>
#include <cstdint>

// ---------------- problem constants ----------------
#define Cdim  512
#define NHd   16
#define HDd   32
#define Ltok  4096
#define Mrows 65536
#define HIDd  2048

// ---------------- scratch (device globals) --------------------------------
// activations in K-blocked, pre-swizzled packed layout (see packed_off)
__device__ __nv_bfloat16 g_xw_h[(size_t)Mrows * Cdim];
__device__ __nv_bfloat16 g_xw_l[(size_t)Mrows * Cdim];
__device__ float         g_qkv [(size_t)Mrows * 3 * Cdim];
__device__ __nv_bfloat16 g_at_h[(size_t)Mrows * Cdim];
__device__ __nv_bfloat16 g_at_l[(size_t)Mrows * Cdim];
__device__ float         g_x2  [(size_t)Mrows * Cdim];
__device__ __nv_bfloat16 g_xm_h[(size_t)Mrows * Cdim];
__device__ __nv_bfloat16 g_xm_l[(size_t)Mrows * Cdim];
__device__ __nv_bfloat16 g_h_h [(size_t)Mrows * HIDd];
__device__ __nv_bfloat16 g_h_l [(size_t)Mrows * HIDd];
__device__ __nv_bfloat16 g_wq_h[1536 * 512], g_wq_l[1536 * 512];
__device__ __nv_bfloat16 g_wp_h[512 * 512],  g_wp_l[512 * 512];
__device__ __nv_bfloat16 g_w1_h[2048 * 512], g_w1_l[2048 * 512];
__device__ __nv_bfloat16 g_w2_h[512 * 2048], g_w2_l[512 * 2048];

// windowed row r -> (batch, natural token l)
__device__ __forceinline__ void win_to_nat(int r, int& bt, int& l) {
    int wb = r >> 6, n = r & 63;
    bt = wb >> 6;
    int wi = wb & 63;
    int hb = wi >> 3, wk = wi & 7;
    l = (((hb << 3) + (n >> 3)) << 6) + (wk << 3) + (n & 7);
}

// K-blocked packed layout with baked-in ldmatrix swizzle.
__device__ __forceinline__ size_t packed_off(int row, int k, int RowsTotal) {
    int kt = k >> 5;
    int ch = (k >> 3) & 3;
    int c7 = (((row & 1) << 2) | ch) ^ ((row >> 1) & 7);
    return (((size_t)kt * RowsTotal + (row & ~1)) << 5) + (c7 << 3) + (k & 7);
}

// ---------------- PTX helpers ---------------------------------------------
__device__ __forceinline__ uint32_t smem_u32(const void* p) {
    uint32_t a;
    asm("{ .reg .u64 t; cvta.to.shared.u64 t, %1; cvt.u32.u64 %0, t; }" : "=r"(a) : "l"(p));
    return a;
}
__device__ __forceinline__ void mbar_init(uint32_t m, uint32_t cnt) {
    asm volatile("mbarrier.init.shared.b64 [%0], %1;" :: "r"(m), "r"(cnt) : "memory");
}
__device__ __forceinline__ void mbar_wait(uint32_t m, uint32_t parity) {
    asm volatile(
        "{\n\t.reg .pred P;\n\t"
        "W_%=:\n\t"
        "mbarrier.try_wait.parity.acquire.cta.shared::cta.b64 P, [%0], %1, 0x989680;\n\t"
        "@P bra D_%=;\n\t"
        "bra W_%=;\n\t"
        "D_%=:\n\t}"
        :: "r"(m), "r"(parity) : "memory");
}
__device__ __forceinline__ void mbar_arrive(uint32_t m) {
    asm volatile("mbarrier.arrive.shared.b64 _, [%0];" :: "r"(m) : "memory");
}
__device__ __forceinline__ void mbar_expect_tx(uint32_t m, uint32_t bytes) {
    asm volatile("mbarrier.arrive.expect_tx.shared.b64 _, [%0], %1;"
                 :: "r"(m), "r"(bytes) : "memory");
}
// battle-tested Hopper form: shared::cluster destination (own CTA smem)
__device__ __forceinline__ void bulk_g2s(uint32_t dst, const void* src,
                                         uint32_t bytes, uint32_t mbar) {
    asm volatile(
        "cp.async.bulk.shared::cluster.global.mbarrier::complete_tx::bytes [%0], [%1], %2, [%3];"
        :: "r"(dst), "l"(src), "r"(bytes), "r"(mbar) : "memory");
}

// consumer-side swizzle (same as packed layout)
__device__ __forceinline__ uint32_t swz(uint32_t off) {
    return off ^ (((off >> 7) & 7) << 4);
}
__device__ __forceinline__ void ldmx4(uint32_t addr, uint32_t& r0, uint32_t& r1,
                                      uint32_t& r2, uint32_t& r3) {
    asm volatile("ldmatrix.sync.aligned.m8n8.x4.shared.b16 {%0,%1,%2,%3}, [%4];"
                 : "=r"(r0), "=r"(r1), "=r"(r2), "=r"(r3) : "r"(addr));
}
__device__ __forceinline__ void mma16816(float* c, const uint32_t* a, const uint32_t* b) {
    asm volatile(
        "mma.sync.aligned.m16n8k16.row.col.f32.bf16.bf16.f32 "
        "{%0,%1,%2,%3}, {%4,%5,%6,%7}, {%8,%9}, {%0,%1,%2,%3};"
        : "+f"(c[0]), "+f"(c[1]), "+f"(c[2]), "+f"(c[3])
        : "r"(a[0]), "r"(a[1]), "r"(a[2]), "r"(a[3]), "r"(b[0]), "r"(b[1]));
}

// ---------------- mma.sync GEMM, bulk-copy loaded --------------------------
// C[M x Nout] = Act[M x K] * W[Nout x K]^T, bf16 hi/lo 3-pass, fp32 regs acc.
// CTA: 128 act rows x 256 out cols, K-tile 32, 8 warps (2M x 4N), warp 64x64.
// 4-stage pipeline, single producer thread, mbarrier full/empty pairs.
#define STG       49152          // Ah 8K | Al 8K | Wh 16K | Wl 16K
#define NSTAGE    4
#define SMEM_TOT  (1024 + NSTAGE * STG)

#define EP_BIAS 0
#define EP_GELU 1
#define EP_PROJ 2
#define EP_ADD  3

__device__ __forceinline__ void issue_stage(
    uint32_t sbase, int kn, int b, int Nout, int bm0, int bn0,
    const __nv_bfloat16* __restrict__ Ah, const __nv_bfloat16* __restrict__ Al,
    const __nv_bfloat16* __restrict__ Wh, const __nv_bfloat16* __restrict__ Wl)
{
    const uint32_t mbar = sbase + b * 8;
    const uint32_t sb = sbase + 1024 + b * STG;
    mbar_expect_tx(mbar, 49152u);
    const size_t aoff = ((size_t)kn * Mrows + bm0) << 6;   // bytes
    const size_t woff = ((size_t)kn * Nout + bn0) << 6;
    bulk_g2s(sb,         (const char*)Ah + aoff, 8192,  mbar);
    bulk_g2s(sb + 8192,  (const char*)Al + aoff, 8192,  mbar);
    bulk_g2s(sb + 16384, (const char*)Wh + woff, 16384, mbar);
    bulk_g2s(sb + 32768, (const char*)Wl + woff, 16384, mbar);
}

template<int EPI>
__global__ void __launch_bounds__(256, 1) tgemm(
    int K, int Nout,
    const __nv_bfloat16* __restrict__ Ah, const __nv_bfloat16* __restrict__ Al,
    const __nv_bfloat16* __restrict__ Wh, const __nv_bfloat16* __restrict__ Wl,
    const float* __restrict__ bias, const float* __restrict__ res,
    float* __restrict__ outf,
    __nv_bfloat16* __restrict__ outh, __nv_bfloat16* __restrict__ outl)
{
    extern __shared__ char smem[];
    const uint32_t sbase = smem_u32(smem);
    const int tid  = threadIdx.x;
    const int bn0  = blockIdx.x * 256;
    const int bm0  = blockIdx.y * 128;
    const int warp = tid >> 5, lane = tid & 31;
    const int wm = (warp >> 2) * 64;
    const int wn = (warp & 3) * 64;

    // full barriers at sbase + b*8 (b<4), empty barriers at sbase + 32 + b*8
    if (tid == 0) {
        #pragma unroll
        for (int s = 0; s < NSTAGE; s++) {
            mbar_init(sbase + s * 8, 1);
            mbar_init(sbase + 32 + s * 8, 256);
        }
        asm volatile("fence.proxy.async.shared::cta;" ::: "memory");
    }
    __syncthreads();

    const int nk = K >> 5;
    if (tid == 0) {
        issue_stage(sbase, 0, 0, Nout, bm0, bn0, Ah, Al, Wh, Wl);
        issue_stage(sbase, 1, 1, Nout, bm0, bn0, Ah, Al, Wh, Wl);
        issue_stage(sbase, 2, 2, Nout, bm0, bn0, Ah, Al, Wh, Wl);
        issue_stage(sbase, 3, 3, Nout, bm0, bn0, Ah, Al, Wh, Wl);
    }

    float acc[4][8][4];
    #pragma unroll
    for (int mf = 0; mf < 4; mf++)
        #pragma unroll
        for (int nf = 0; nf < 8; nf++)
            #pragma unroll
            for (int u = 0; u < 4; u++) acc[mf][nf][u] = 0.0f;

    const int rA = wm + (lane & 15);
    const int rB = wn + (lane & 15);
    const int cb = lane >> 4;

    for (int kt = 0; kt < nk; kt++) {
        const int b = kt & 3;
        const int cyc = kt >> 2;
        mbar_wait(sbase + b * 8, cyc & 1);

        const uint32_t sg = sbase + 1024 + b * STG;
        const uint32_t aT[2] = { sg, sg + 8192 };           // act hi, lo
        const uint32_t wT[2] = { sg + 16384, sg + 32768 };  // w hi, lo
        #pragma unroll
        for (int p = 0; p < 3; p++) {
            const uint32_t at = aT[p == 1];
            const uint32_t wt = wT[p == 2];
            #pragma unroll
            for (int kf = 0; kf < 2; kf++) {
                const int ch = kf * 2 + cb;
                uint32_t a[4][4];
                #pragma unroll
                for (int mf = 0; mf < 4; mf++)
                    ldmx4(at + swz((rA + mf * 16) * 64 + ch * 16),
                          a[mf][0], a[mf][1], a[mf][2], a[mf][3]);
                uint32_t b2[8][2];
                #pragma unroll
                for (int n2 = 0; n2 < 4; n2++) {
                    uint32_t r0, r1, r2, r3;
                    ldmx4(wt + swz((rB + n2 * 16) * 64 + ch * 16), r0, r1, r2, r3);
                    b2[2 * n2][0] = r0; b2[2 * n2][1] = r2;
                    b2[2 * n2 + 1][0] = r1; b2[2 * n2 + 1][1] = r3;
                }
                #pragma unroll
                for (int mf = 0; mf < 4; mf++)
                    #pragma unroll
                    for (int nf = 0; nf < 8; nf++)
                        mma16816(acc[mf][nf], a[mf], b2[nf]);
            }
        }
        mbar_arrive(sbase + 32 + b * 8);
        if (tid == 0 && kt + NSTAGE < nk) {
            mbar_wait(sbase + 32 + b * 8, cyc & 1);
            issue_stage(sbase, kt + NSTAGE, b, Nout, bm0, bn0, Ah, Al, Wh, Wl);
        }
    }

    // ---------------- epilogue ----------------
    const int g = lane >> 2, q = lane & 3;
    #pragma unroll
    for (int mf = 0; mf < 4; mf++) {
        const int row0 = bm0 + wm + mf * 16 + g;
        const int row1 = row0 + 8;
        size_t ob0, ob1;
        if (EPI == EP_PROJ) {
            int bt, l;
            win_to_nat(row0, bt, l); ob0 = ((size_t)bt * Ltok + l) * (size_t)Nout;
            win_to_nat(row1, bt, l); ob1 = ((size_t)bt * Ltok + l) * (size_t)Nout;
        } else {
            ob0 = (size_t)row0 * Nout;
            ob1 = (size_t)row1 * Nout;
        }
        #pragma unroll
        for (int nf = 0; nf < 8; nf++) {
            const int col = bn0 + wn + nf * 8 + q * 2;
            const float b0 = bias[col], b1 = bias[col + 1];
            float v00 = acc[mf][nf][0] + b0, v01 = acc[mf][nf][1] + b1;
            float v10 = acc[mf][nf][2] + b0, v11 = acc[mf][nf][3] + b1;
            if (EPI == EP_BIAS) {
                *(float2*)(outf + ob0 + col) = make_float2(v00, v01);
                *(float2*)(outf + ob1 + col) = make_float2(v10, v11);
            } else if (EPI == EP_GELU) {
                v00 = 0.5f * v00 * (1.0f + erff(v00 * 0.70710678118654752f));
                v01 = 0.5f * v01 * (1.0f + erff(v01 * 0.70710678118654752f));
                v10 = 0.5f * v10 * (1.0f + erff(v10 * 0.70710678118654752f));
                v11 = 0.5f * v11 * (1.0f + erff(v11 * 0.70710678118654752f));
                __nv_bfloat16 h00 = __float2bfloat16_rn(v00), h01 = __float2bfloat16_rn(v01);
                __nv_bfloat16 h10 = __float2bfloat16_rn(v10), h11 = __float2bfloat16_rn(v11);
                size_t p0 = packed_off(row0, col, Mrows);
                size_t p1 = packed_off(row1, col, Mrows);
                *(__nv_bfloat162*)(outh + p0) = __nv_bfloat162(h00, h01);
                *(__nv_bfloat162*)(outh + p1) = __nv_bfloat162(h10, h11);
                *(__nv_bfloat162*)(outl + p0) = __nv_bfloat162(
                    __float2bfloat16_rn(v00 - __bfloat162float(h00)),
                    __float2bfloat16_rn(v01 - __bfloat162float(h01)));
                *(__nv_bfloat162*)(outl + p1) = __nv_bfloat162(
                    __float2bfloat16_rn(v10 - __bfloat162float(h10)),
                    __float2bfloat16_rn(v11 - __bfloat162float(h11)));
            } else {  // EP_PROJ / EP_ADD: += residual
                float2 r0 = *(const float2*)(res + ob0 + col);
                float2 r1 = *(const float2*)(res + ob1 + col);
                *(float2*)(outf + ob0 + col) = make_float2(v00 + r0.x, v01 + r0.y);
                *(float2*)(outf + ob1 + col) = make_float2(v10 + r1.x, v11 + r1.y);
            }
        }
    }
}

// ---------------- fp32 -> bf16 hi/lo weight conversion (packed) -----------
__global__ __launch_bounds__(256) void cvt_w(
    const float* __restrict__ src, __nv_bfloat16* __restrict__ hi,
    __nv_bfloat16* __restrict__ lo, int Rows, int K)
{
    int i = blockIdx.x * 256 + threadIdx.x;   // 16B-chunk id
    int cpr = K >> 3;
    int n = i / cpr;
    int kc = (i - n * cpr) << 3;
    const float4* s = (const float4*)(src + (size_t)n * K + kc);
    float4 v0 = s[0], v1 = s[1];
    float vv[8] = { v0.x, v0.y, v0.z, v0.w, v1.x, v1.y, v1.z, v1.w };
    __nv_bfloat16 h[8], l[8];
    #pragma unroll
    for (int u = 0; u < 8; u++) {
        h[u] = __float2bfloat16_rn(vv[u]);
        l[u] = __float2bfloat16_rn(vv[u] - __bfloat162float(h[u]));
    }
    size_t o = packed_off(n, kc, Rows);
    *(uint4*)(hi + o) = *(uint4*)h;
    *(uint4*)(lo + o) = *(uint4*)l;
}

// ---------------- LayerNorm -> bf16 hi/lo pair (packed) -------------------
__global__ __launch_bounds__(128) void ln_kernel(
    const float* __restrict__ x, const float* __restrict__ g,
    const float* __restrict__ b, __nv_bfloat16* __restrict__ outh,
    __nv_bfloat16* __restrict__ outl, int windowed)
{
    int r = blockIdx.x;
    size_t ibase;
    if (windowed) {
        int bt, l; win_to_nat(r, bt, l);
        ibase = ((size_t)bt * Ltok + l) * Cdim;
    } else {
        ibase = (size_t)r * Cdim;
    }
    int t = threadIdx.x;
    float4 v = *(const float4*)(x + ibase + t * 4);
    float s  = v.x + v.y + v.z + v.w;
    float sq = v.x*v.x + v.y*v.y + v.z*v.z + v.w*v.w;
    #pragma unroll
    for (int off = 16; off; off >>= 1) {
        s  += __shfl_xor_sync(0xffffffffu, s,  off);
        sq += __shfl_xor_sync(0xffffffffu, sq, off);
    }
    __shared__ float ws[4], wq[4];
    int wid = t >> 5, lane = t & 31;
    if (lane == 0) { ws[wid] = s; wq[wid] = sq; }
    __syncthreads();
    s  = ws[0] + ws[1] + ws[2] + ws[3];
    sq = wq[0] + wq[1] + wq[2] + wq[3];
    float mean = s * (1.0f / 512.0f);
    float var  = sq * (1.0f / 512.0f) - mean * mean;
    float rstd = rsqrtf(var + 1e-5f);
    float4 gg = *(const float4*)(g + t * 4);
    float4 bb = *(const float4*)(b + t * 4);
    float ov[4];
    ov[0] = (v.x - mean) * rstd * gg.x + bb.x;
    ov[1] = (v.y - mean) * rstd * gg.y + bb.y;
    ov[2] = (v.z - mean) * rstd * gg.z + bb.z;
    ov[3] = (v.w - mean) * rstd * gg.w + bb.w;
    __nv_bfloat16 hv[4], lv[4];
    #pragma unroll
    for (int u = 0; u < 4; u++) {
        hv[u] = __float2bfloat16_rn(ov[u]);
        lv[u] = __float2bfloat16_rn(ov[u] - __bfloat162float(hv[u]));
    }
    size_t o = packed_off(r, t * 4, Mrows);   // 4 elems within one 16B chunk
    *(uint2*)(outh + o) = *(uint2*)hv;
    *(uint2*)(outl + o) = *(uint2*)lv;
}

// ---------------- fused windowed attention (packed bf16 pair out) ---------
#define QSCALE 0.17677669529663687f
#define AZC    0.09817477042468103f
#define RDC    0.02454369260617026f

__global__ __launch_bounds__(256) void attn_kernel(
    const float* __restrict__ qkv, const float* __restrict__ Dp,
    const float* __restrict__ a_p, const float* __restrict__ b_p,
    const float* __restrict__ a_r, const float* __restrict__ b_r,
    __nv_bfloat16* __restrict__ outh, __nv_bfloat16* __restrict__ outl)
{
    __shared__ float QK[4224];
    __shared__ float Vs[64][33];
    __shared__ float csr[15][64];
    __shared__ float ssr[15][64];
    __shared__ float arh[15], brh[15], phs[15];

    const int wb  = blockIdx.x;
    const int h   = blockIdx.y;
    const int tid = threadIdx.x;
    float* Qs = QK;
    float* Ks = QK + 64 * 33;

    for (int v = tid; v < 512; v += 256) {
        int n = v >> 3, d4 = (v & 7) << 2;
        size_t base = ((size_t)(wb * 64 + n)) * 1536 + h * 32 + d4;
        float4 q4 = *(const float4*)(qkv + base);
        Qs[n * 33 + d4 + 0] = q4.x * QSCALE;
        Qs[n * 33 + d4 + 1] = q4.y * QSCALE;
        Qs[n * 33 + d4 + 2] = q4.z * QSCALE;
        Qs[n * 33 + d4 + 3] = q4.w * QSCALE;
        float4 k4 = *(const float4*)(qkv + base + 512);
        Ks[n * 33 + d4 + 0] = k4.x; Ks[n * 33 + d4 + 1] = k4.y;
        Ks[n * 33 + d4 + 2] = k4.z; Ks[n * 33 + d4 + 3] = k4.w;
        float4 v4 = *(const float4*)(qkv + base + 1024);
        Vs[n][d4 + 0] = v4.x; Vs[n][d4 + 1] = v4.y;
        Vs[n][d4 + 2] = v4.z; Vs[n][d4 + 3] = v4.w;
    }
    {
        int bt = wb >> 6, wi = wb & 63, hb = wi >> 3, wk = wi & 7;
        for (int v = tid; v < 960; v += 256) {
            int dyp = v >> 6, jj = v & 63;
            float Dv = Dp[bt * 4096 + (((hb << 3) + (jj >> 3)) << 6) + (wk << 3) + (jj & 7)];
            float ang = (float)(dyp - 7) * Dv * RDC;
            float sn, cs; __sincosf(ang, &sn, &cs);
            csr[dyp][jj] = cs; ssr[dyp][jj] = sn;
        }
    }
    if (tid < 15) {
        arh[tid] = a_r[tid * NHd + h];
        brh[tid] = b_r[tid * NHd + h];
        int dx = tid - 7;
        int ip = dx < 0 ? dx + 15 : dx;
        float azf = (float)dx * AZC;
        float sn, cs; __sincosf(azf, &sn, &cs);
        phs[tid] = a_p[ip * NHd + h] * cs + b_p[ip * NHd + h] * sn;
    }
    __syncthreads();

    const int j = tid & 63, ig = tid >> 6;
    float acc[16];
    #pragma unroll
    for (int ii = 0; ii < 16; ii++) acc[ii] = 0.0f;
    #pragma unroll 8
    for (int d = 0; d < 32; d++) {
        float kv = Ks[j * 33 + d];
        #pragma unroll
        for (int ii = 0; ii < 16; ii++)
            acc[ii] += Qs[(ig * 16 + ii) * 33 + d] * kv;
    }
    const int yj = j >> 3, xjm = j & 7;
    #pragma unroll
    for (int ii = 0; ii < 16; ii++) {
        int i = ig * 16 + ii;
        int dy = (i >> 3) - yj;
        int dyp = dy + 7;
        int ir = dy < 0 ? dy + 15 : dy;
        int dxp = (i & 7) - xjm + 7;
        acc[ii] += phs[dxp] + arh[ir] * csr[dyp][j] + brh[ir] * ssr[dyp][j];
    }
    __syncthreads();
    float* Ss = QK;
    #pragma unroll
    for (int ii = 0; ii < 16; ii++) Ss[(ig * 16 + ii) * 65 + j] = acc[ii];
    __syncthreads();

    {
        int i = tid >> 2, p = tid & 3;
        float vals[16];
        float mx = -1e30f;
        #pragma unroll
        for (int u = 0; u < 16; u++) { vals[u] = Ss[i * 65 + p * 16 + u]; mx = fmaxf(mx, vals[u]); }
        mx = fmaxf(mx, __shfl_xor_sync(0xffffffffu, mx, 1));
        mx = fmaxf(mx, __shfl_xor_sync(0xffffffffu, mx, 2));
        float sm = 0.0f;
        #pragma unroll
        for (int u = 0; u < 16; u++) { vals[u] = __expf(vals[u] - mx); sm += vals[u]; }
        sm += __shfl_xor_sync(0xffffffffu, sm, 1);
        sm += __shfl_xor_sync(0xffffffffu, sm, 2);
        float inv = 1.0f / sm;
        #pragma unroll
        for (int u = 0; u < 16; u++) Ss[i * 65 + p * 16 + u] = vals[u] * inv;
    }
    __syncthreads();

    {
        int d = tid & 31, ig2 = tid >> 5;
        float acc2[8];
        #pragma unroll
        for (int u = 0; u < 8; u++) acc2[u] = 0.0f;
        #pragma unroll 4
        for (int m = 0; m < 64; m++) {
            float vv = Vs[m][d];
            #pragma unroll
            for (int u = 0; u < 8; u++)
                acc2[u] += Ss[(ig2 * 8 + u) * 65 + m] * vv;
        }
        #pragma unroll
        for (int u = 0; u < 8; u++) {
            int i = ig2 * 8 + u;
            int row = wb * 64 + i;
            float v = acc2[u];
            __nv_bfloat16 hh = __float2bfloat16_rn(v);
            size_t o = packed_off(row, h * 32 + d, Mrows);
            outh[o] = hh;
            outl[o] = __float2bfloat16_rn(v - __bfloat162float(hh));
        }
    }
}

// ---------------- launch -------------------------------------------------
extern "C" void kernel_launch(void* const* d_in, const int* in_sizes, int n_in,
                              void* d_out, int out_size) {
    (void)in_sizes; (void)n_in; (void)out_size;
    const float* x      = (const float*)d_in[0];
    const float* D      = (const float*)d_in[1];
    const float* n1g    = (const float*)d_in[2];
    const float* n1b    = (const float*)d_in[3];
    const float* qkv_w  = (const float*)d_in[4];
    const float* qkv_b  = (const float*)d_in[5];
    const float* proj_w = (const float*)d_in[6];
    const float* proj_b = (const float*)d_in[7];
    const float* a_p    = (const float*)d_in[8];
    const float* b_p    = (const float*)d_in[9];
    const float* a_r    = (const float*)d_in[10];
    const float* b_r    = (const float*)d_in[11];
    const float* n2g    = (const float*)d_in[12];
    const float* n2b    = (const float*)d_in[13];
    const float* fc1_w  = (const float*)d_in[14];
    const float* fc1_b  = (const float*)d_in[15];
    const float* fc2_w  = (const float*)d_in[16];
    const float* fc2_b  = (const float*)d_in[17];
    float* out = (float*)d_out;

    __nv_bfloat16 *xwh, *xwl, *ath, *atl, *xmh, *xml, *hh, *hl;
    __nv_bfloat16 *wqh, *wql, *wph, *wpl, *w1h, *w1l, *w2h, *w2l;
    float *qkvb, *x2;
    cudaGetSymbolAddress((void**)&xwh, g_xw_h); cudaGetSymbolAddress((void**)&xwl, g_xw_l);
    cudaGetSymbolAddress((void**)&ath, g_at_h); cudaGetSymbolAddress((void**)&atl, g_at_l);
    cudaGetSymbolAddress((void**)&xmh, g_xm_h); cudaGetSymbolAddress((void**)&xml, g_xm_l);
    cudaGetSymbolAddress((void**)&hh,  g_h_h);  cudaGetSymbolAddress((void**)&hl,  g_h_l);
    cudaGetSymbolAddress((void**)&wqh, g_wq_h); cudaGetSymbolAddress((void**)&wql, g_wq_l);
    cudaGetSymbolAddress((void**)&wph, g_wp_h); cudaGetSymbolAddress((void**)&wpl, g_wp_l);
    cudaGetSymbolAddress((void**)&w1h, g_w1_h); cudaGetSymbolAddress((void**)&w1l, g_w1_l);
    cudaGetSymbolAddress((void**)&w2h, g_w2_h); cudaGetSymbolAddress((void**)&w2l, g_w2_l);
    cudaGetSymbolAddress((void**)&qkvb, g_qkv); cudaGetSymbolAddress((void**)&x2, g_x2);

    cudaFuncSetAttribute(tgemm<EP_BIAS>, cudaFuncAttributeMaxDynamicSharedMemorySize, SMEM_TOT);
    cudaFuncSetAttribute(tgemm<EP_GELU>, cudaFuncAttributeMaxDynamicSharedMemorySize, SMEM_TOT);
    cudaFuncSetAttribute(tgemm<EP_PROJ>, cudaFuncAttributeMaxDynamicSharedMemorySize, SMEM_TOT);
    cudaFuncSetAttribute(tgemm<EP_ADD>,  cudaFuncAttributeMaxDynamicSharedMemorySize, SMEM_TOT);

    // weight conversions into packed layout
    cvt_w<<<(1536 * 512 / 8) / 256, 256>>>(qkv_w,  wqh, wql, 1536, 512);
    cvt_w<<<(512 * 512 / 8)  / 256, 256>>>(proj_w, wph, wpl, 512,  512);
    cvt_w<<<(2048 * 512 / 8) / 256, 256>>>(fc1_w,  w1h, w1l, 2048, 512);
    cvt_w<<<(512 * 2048 / 8) / 256, 256>>>(fc2_w,  w2h, w2l, 512,  2048);

    // 1) LN1 + window partition -> packed bf16 pair
    ln_kernel<<<Mrows, 128>>>(x, n1g, n1b, xwh, xwl, 1);
    // 2) QKV GEMM
    tgemm<EP_BIAS><<<dim3(1536 / 256, Mrows / 128), 256, SMEM_TOT>>>(
        512, 1536, xwh, xwl, wqh, wql, qkv_b, nullptr, qkvb, nullptr, nullptr);
    // 3) fused windowed attention -> packed bf16 pair
    attn_kernel<<<dim3(1024, 16), 256>>>(qkvb, D, a_p, b_p, a_r, b_r, ath, atl);
    // 4) proj GEMM + window reverse + residual
    tgemm<EP_PROJ><<<dim3(512 / 256, Mrows / 128), 256, SMEM_TOT>>>(
        512, 512, ath, atl, wph, wpl, proj_b, x, x2, nullptr, nullptr);
    // 5) LN2 -> packed bf16 pair
    ln_kernel<<<Mrows, 128>>>(x2, n2g, n2b, xmh, xml, 0);
    // 6) fc1 + GELU -> packed bf16 pair
    tgemm<EP_GELU><<<dim3(2048 / 256, Mrows / 128), 256, SMEM_TOT>>>(
        512, 2048, xmh, xml, w1h, w1l, fc1_b, nullptr, nullptr, hh, hl);
    // 7) fc2 + residual -> output
    tgemm<EP_ADD><<<dim3(512 / 256, Mrows / 128), 256, SMEM_TOT>>>(
        2048, 512, hh, hl, w2h, w2l, fc2_b, x2, out, nullptr, nullptr);
}

// round 9
// speedup vs baseline: 4.0400x; 1.4549x over previous
#include <cuda_runtime.h>
#include <cuda_fp16.h>
#include <cstdint>

// ---------------- problem constants ----------------
#define Cdim  512
#define NHd   16
#define HDd   32
#define Ltok  4096
#define Mrows 65536
#define HIDd  2048

// ---------------- scratch (device globals) --------------------------------
// activations: single fp16, K-blocked pre-swizzled packed layout (packed_off)
__device__ __half g_xw[(size_t)Mrows * Cdim];
__device__ float  g_qkv[(size_t)Mrows * 3 * Cdim];
__device__ __half g_at[(size_t)Mrows * Cdim];
__device__ float  g_x2[(size_t)Mrows * Cdim];
__device__ __half g_xm[(size_t)Mrows * Cdim];
__device__ __half g_h [(size_t)Mrows * HIDd];
// weights: fp16 hi/lo pairs, packed layout
__device__ __half g_wq_h[1536 * 512], g_wq_l[1536 * 512];
__device__ __half g_wp_h[512 * 512],  g_wp_l[512 * 512];
__device__ __half g_w1_h[2048 * 512], g_w1_l[2048 * 512];
__device__ __half g_w2_h[512 * 2048], g_w2_l[512 * 2048];

// windowed row r -> (batch, natural token l)
__device__ __forceinline__ void win_to_nat(int r, int& bt, int& l) {
    int wb = r >> 6, n = r & 63;
    bt = wb >> 6;
    int wi = wb & 63;
    int hb = wi >> 3, wk = wi & 7;
    l = (((hb << 3) + (n >> 3)) << 6) + (wk << 3) + (n & 7);
}

// K-blocked packed layout with baked-in ldmatrix swizzle.
__device__ __forceinline__ size_t packed_off(int row, int k, int RowsTotal) {
    int kt = k >> 5;
    int ch = (k >> 3) & 3;
    int c7 = (((row & 1) << 2) | ch) ^ ((row >> 1) & 7);
    return (((size_t)kt * RowsTotal + (row & ~1)) << 5) + (c7 << 3) + (k & 7);
}

// ---------------- PTX helpers ---------------------------------------------
__device__ __forceinline__ uint32_t smem_u32(const void* p) {
    uint32_t a;
    asm("{ .reg .u64 t; cvta.to.shared.u64 t, %1; cvt.u32.u64 %0, t; }" : "=r"(a) : "l"(p));
    return a;
}
__device__ __forceinline__ void mbar_init(uint32_t m, uint32_t cnt) {
    asm volatile("mbarrier.init.shared.b64 [%0], %1;" :: "r"(m), "r"(cnt) : "memory");
}
__device__ __forceinline__ void mbar_wait(uint32_t m, uint32_t parity) {
    asm volatile(
        "{\n\t.reg .pred P;\n\t"
        "W_%=:\n\t"
        "mbarrier.try_wait.parity.acquire.cta.shared::cta.b64 P, [%0], %1, 0x989680;\n\t"
        "@P bra D_%=;\n\t"
        "bra W_%=;\n\t"
        "D_%=:\n\t}"
        :: "r"(m), "r"(parity) : "memory");
}
__device__ __forceinline__ void mbar_arrive(uint32_t m) {
    asm volatile("mbarrier.arrive.shared.b64 _, [%0];" :: "r"(m) : "memory");
}
__device__ __forceinline__ void mbar_expect_tx(uint32_t m, uint32_t bytes) {
    asm volatile("mbarrier.arrive.expect_tx.shared.b64 _, [%0], %1;"
                 :: "r"(m), "r"(bytes) : "memory");
}
__device__ __forceinline__ void bulk_g2s(uint32_t dst, const void* src,
                                         uint32_t bytes, uint32_t mbar) {
    asm volatile(
        "cp.async.bulk.shared::cluster.global.mbarrier::complete_tx::bytes [%0], [%1], %2, [%3];"
        :: "r"(dst), "l"(src), "r"(bytes), "r"(mbar) : "memory");
}

__device__ __forceinline__ uint32_t swz(uint32_t off) {
    return off ^ (((off >> 7) & 7) << 4);
}
__device__ __forceinline__ void ldmx4(uint32_t addr, uint32_t& r0, uint32_t& r1,
                                      uint32_t& r2, uint32_t& r3) {
    asm volatile("ldmatrix.sync.aligned.m8n8.x4.shared.b16 {%0,%1,%2,%3}, [%4];"
                 : "=r"(r0), "=r"(r1), "=r"(r2), "=r"(r3) : "r"(addr));
}
__device__ __forceinline__ void mma16816(float* c, const uint32_t* a, const uint32_t* b) {
    asm volatile(
        "mma.sync.aligned.m16n8k16.row.col.f32.f16.f16.f32 "
        "{%0,%1,%2,%3}, {%4,%5,%6,%7}, {%8,%9}, {%0,%1,%2,%3};"
        : "+f"(c[0]), "+f"(c[1]), "+f"(c[2]), "+f"(c[3])
        : "r"(a[0]), "r"(a[1]), "r"(a[2]), "r"(a[3]), "r"(b[0]), "r"(b[1]));
}

// ---------------- mma.sync GEMM, bulk-copy loaded --------------------------
// C[M x Nout] = Act[M x K] * W[Nout x K]^T.
// Act: single fp16.  W: fp16 hi/lo pair -> 2 MMA passes (A*Wh + A*Wl = A*W).
// CTA: 128 act rows x 256 out cols, K-tile 32, 8 warps (2M x 4N), warp 64x64.
#define STG       40960          // A 8K | Wh 16K | Wl 16K
#define NSTAGE    4
#define SMEM_TOT  (1024 + NSTAGE * STG)

#define EP_BIAS 0
#define EP_GELU 1
#define EP_PROJ 2
#define EP_ADD  3

__device__ __forceinline__ void issue_stage(
    uint32_t sbase, int kn, int b, int Nout, int bm0, int bn0,
    const __half* __restrict__ A,
    const __half* __restrict__ Wh, const __half* __restrict__ Wl)
{
    const uint32_t mbar = sbase + b * 8;
    const uint32_t sb = sbase + 1024 + b * STG;
    mbar_expect_tx(mbar, 40960u);
    const size_t aoff = ((size_t)kn * Mrows + bm0) << 6;   // bytes
    const size_t woff = ((size_t)kn * Nout + bn0) << 6;
    bulk_g2s(sb,         (const char*)A  + aoff, 8192,  mbar);
    bulk_g2s(sb + 8192,  (const char*)Wh + woff, 16384, mbar);
    bulk_g2s(sb + 24576, (const char*)Wl + woff, 16384, mbar);
}

template<int EPI>
__global__ void __launch_bounds__(256, 1) tgemm(
    int K, int Nout,
    const __half* __restrict__ A,
    const __half* __restrict__ Wh, const __half* __restrict__ Wl,
    const float* __restrict__ bias, const float* __restrict__ res,
    float* __restrict__ outf, __half* __restrict__ outh)
{
    extern __shared__ char smem[];
    const uint32_t sbase = smem_u32(smem);
    const int tid  = threadIdx.x;
    const int bn0  = blockIdx.x * 256;
    const int bm0  = blockIdx.y * 128;
    const int warp = tid >> 5, lane = tid & 31;
    const int wm = (warp >> 2) * 64;
    const int wn = (warp & 3) * 64;

    if (tid == 0) {
        #pragma unroll
        for (int s = 0; s < NSTAGE; s++) {
            mbar_init(sbase + s * 8, 1);
            mbar_init(sbase + 32 + s * 8, 256);
        }
        asm volatile("fence.proxy.async.shared::cta;" ::: "memory");
    }
    __syncthreads();

    const int nk = K >> 5;
    if (tid == 0) {
        issue_stage(sbase, 0, 0, Nout, bm0, bn0, A, Wh, Wl);
        issue_stage(sbase, 1, 1, Nout, bm0, bn0, A, Wh, Wl);
        issue_stage(sbase, 2, 2, Nout, bm0, bn0, A, Wh, Wl);
        issue_stage(sbase, 3, 3, Nout, bm0, bn0, A, Wh, Wl);
    }

    float acc[4][8][4];
    #pragma unroll
    for (int mf = 0; mf < 4; mf++)
        #pragma unroll
        for (int nf = 0; nf < 8; nf++)
            #pragma unroll
            for (int u = 0; u < 4; u++) acc[mf][nf][u] = 0.0f;

    const int rA = wm + (lane & 15);
    const int rB = wn + (lane & 15);
    const int cb = lane >> 4;

    for (int kt = 0; kt < nk; kt++) {
        const int b = kt & 3;
        const int cyc = kt >> 2;
        mbar_wait(sbase + b * 8, cyc & 1);

        const uint32_t sg = sbase + 1024 + b * STG;
        const uint32_t at = sg;
        const uint32_t wT[2] = { sg + 8192, sg + 24576 };
        #pragma unroll
        for (int kf = 0; kf < 2; kf++) {
            const int ch = kf * 2 + cb;
            uint32_t a[4][4];
            #pragma unroll
            for (int mf = 0; mf < 4; mf++)
                ldmx4(at + swz((rA + mf * 16) * 64 + ch * 16),
                      a[mf][0], a[mf][1], a[mf][2], a[mf][3]);
            #pragma unroll
            for (int p = 0; p < 2; p++) {
                const uint32_t wt = wT[p];
                uint32_t b2[8][2];
                #pragma unroll
                for (int n2 = 0; n2 < 4; n2++) {
                    uint32_t r0, r1, r2, r3;
                    ldmx4(wt + swz((rB + n2 * 16) * 64 + ch * 16), r0, r1, r2, r3);
                    b2[2 * n2][0] = r0; b2[2 * n2][1] = r2;
                    b2[2 * n2 + 1][0] = r1; b2[2 * n2 + 1][1] = r3;
                }
                #pragma unroll
                for (int mf = 0; mf < 4; mf++)
                    #pragma unroll
                    for (int nf = 0; nf < 8; nf++)
                        mma16816(acc[mf][nf], a[mf], b2[nf]);
            }
        }
        mbar_arrive(sbase + 32 + b * 8);
        if (tid == 0 && kt + NSTAGE < nk) {
            mbar_wait(sbase + 32 + b * 8, cyc & 1);
            issue_stage(sbase, kt + NSTAGE, b, Nout, bm0, bn0, A, Wh, Wl);
        }
    }

    // ---------------- epilogue ----------------
    const int g = lane >> 2, q = lane & 3;
    #pragma unroll
    for (int mf = 0; mf < 4; mf++) {
        const int row0 = bm0 + wm + mf * 16 + g;
        const int row1 = row0 + 8;
        size_t ob0, ob1;
        if (EPI == EP_PROJ) {
            int bt, l;
            win_to_nat(row0, bt, l); ob0 = ((size_t)bt * Ltok + l) * (size_t)Nout;
            win_to_nat(row1, bt, l); ob1 = ((size_t)bt * Ltok + l) * (size_t)Nout;
        } else {
            ob0 = (size_t)row0 * Nout;
            ob1 = (size_t)row1 * Nout;
        }
        #pragma unroll
        for (int nf = 0; nf < 8; nf++) {
            const int col = bn0 + wn + nf * 8 + q * 2;
            const float b0 = bias[col], b1 = bias[col + 1];
            float v00 = acc[mf][nf][0] + b0, v01 = acc[mf][nf][1] + b1;
            float v10 = acc[mf][nf][2] + b0, v11 = acc[mf][nf][3] + b1;
            if (EPI == EP_BIAS) {
                *(float2*)(outf + ob0 + col) = make_float2(v00, v01);
                *(float2*)(outf + ob1 + col) = make_float2(v10, v11);
            } else if (EPI == EP_GELU) {
                v00 = 0.5f * v00 * (1.0f + erff(v00 * 0.70710678118654752f));
                v01 = 0.5f * v01 * (1.0f + erff(v01 * 0.70710678118654752f));
                v10 = 0.5f * v10 * (1.0f + erff(v10 * 0.70710678118654752f));
                v11 = 0.5f * v11 * (1.0f + erff(v11 * 0.70710678118654752f));
                size_t p0 = packed_off(row0, col, Mrows);
                size_t p1 = packed_off(row1, col, Mrows);
                *(__half2*)(outh + p0) = __halves2half2(__float2half_rn(v00), __float2half_rn(v01));
                *(__half2*)(outh + p1) = __halves2half2(__float2half_rn(v10), __float2half_rn(v11));
            } else {  // EP_PROJ / EP_ADD: += residual
                float2 r0 = *(const float2*)(res + ob0 + col);
                float2 r1 = *(const float2*)(res + ob1 + col);
                *(float2*)(outf + ob0 + col) = make_float2(v00 + r0.x, v01 + r0.y);
                *(float2*)(outf + ob1 + col) = make_float2(v10 + r1.x, v11 + r1.y);
            }
        }
    }
}

// ---------------- fp32 -> fp16 hi/lo weight conversion (packed) -----------
__global__ __launch_bounds__(256) void cvt_w(
    const float* __restrict__ src, __half* __restrict__ hi,
    __half* __restrict__ lo, int Rows, int K)
{
    int i = blockIdx.x * 256 + threadIdx.x;   // 16B-chunk id
    int cpr = K >> 3;
    int n = i / cpr;
    int kc = (i - n * cpr) << 3;
    const float4* s = (const float4*)(src + (size_t)n * K + kc);
    float4 v0 = s[0], v1 = s[1];
    float vv[8] = { v0.x, v0.y, v0.z, v0.w, v1.x, v1.y, v1.z, v1.w };
    __half h[8], l[8];
    #pragma unroll
    for (int u = 0; u < 8; u++) {
        h[u] = __float2half_rn(vv[u]);
        l[u] = __float2half_rn(vv[u] - __half2float(h[u]));
    }
    size_t o = packed_off(n, kc, Rows);
    *(uint4*)(hi + o) = *(uint4*)h;
    *(uint4*)(lo + o) = *(uint4*)l;
}

// ---------------- LayerNorm -> fp16 (packed) ------------------------------
__global__ __launch_bounds__(128) void ln_kernel(
    const float* __restrict__ x, const float* __restrict__ g,
    const float* __restrict__ b, __half* __restrict__ outh, int windowed)
{
    int r = blockIdx.x;
    size_t ibase;
    if (windowed) {
        int bt, l; win_to_nat(r, bt, l);
        ibase = ((size_t)bt * Ltok + l) * Cdim;
    } else {
        ibase = (size_t)r * Cdim;
    }
    int t = threadIdx.x;
    float4 v = *(const float4*)(x + ibase + t * 4);
    float s  = v.x + v.y + v.z + v.w;
    float sq = v.x*v.x + v.y*v.y + v.z*v.z + v.w*v.w;
    #pragma unroll
    for (int off = 16; off; off >>= 1) {
        s  += __shfl_xor_sync(0xffffffffu, s,  off);
        sq += __shfl_xor_sync(0xffffffffu, sq, off);
    }
    __shared__ float ws[4], wq[4];
    int wid = t >> 5, lane = t & 31;
    if (lane == 0) { ws[wid] = s; wq[wid] = sq; }
    __syncthreads();
    s  = ws[0] + ws[1] + ws[2] + ws[3];
    sq = wq[0] + wq[1] + wq[2] + wq[3];
    float mean = s * (1.0f / 512.0f);
    float var  = sq * (1.0f / 512.0f) - mean * mean;
    float rstd = rsqrtf(var + 1e-5f);
    float4 gg = *(const float4*)(g + t * 4);
    float4 bb = *(const float4*)(b + t * 4);
    __half hv[4];
    hv[0] = __float2half_rn((v.x - mean) * rstd * gg.x + bb.x);
    hv[1] = __float2half_rn((v.y - mean) * rstd * gg.y + bb.y);
    hv[2] = __float2half_rn((v.z - mean) * rstd * gg.z + bb.z);
    hv[3] = __float2half_rn((v.w - mean) * rstd * gg.w + bb.w);
    size_t o = packed_off(r, t * 4, Mrows);
    *(uint2*)(outh + o) = *(uint2*)hv;
}

// ---------------- fused windowed attention (fp16 packed out) --------------
#define QSCALE 0.17677669529663687f
#define AZC    0.09817477042468103f
#define RDC    0.02454369260617026f

__global__ __launch_bounds__(256) void attn_kernel(
    const float* __restrict__ qkv, const float* __restrict__ Dp,
    const float* __restrict__ a_p, const float* __restrict__ b_p,
    const float* __restrict__ a_r, const float* __restrict__ b_r,
    __half* __restrict__ outh)
{
    __shared__ float QK[4224];
    __shared__ float Vs[64][33];
    __shared__ float csr[15][64];
    __shared__ float ssr[15][64];
    __shared__ float arh[15], brh[15], phs[15];

    const int wb  = blockIdx.x;
    const int h   = blockIdx.y;
    const int tid = threadIdx.x;
    float* Qs = QK;
    float* Ks = QK + 64 * 33;

    for (int v = tid; v < 512; v += 256) {
        int n = v >> 3, d4 = (v & 7) << 2;
        size_t base = ((size_t)(wb * 64 + n)) * 1536 + h * 32 + d4;
        float4 q4 = *(const float4*)(qkv + base);
        Qs[n * 33 + d4 + 0] = q4.x * QSCALE;
        Qs[n * 33 + d4 + 1] = q4.y * QSCALE;
        Qs[n * 33 + d4 + 2] = q4.z * QSCALE;
        Qs[n * 33 + d4 + 3] = q4.w * QSCALE;
        float4 k4 = *(const float4*)(qkv + base + 512);
        Ks[n * 33 + d4 + 0] = k4.x; Ks[n * 33 + d4 + 1] = k4.y;
        Ks[n * 33 + d4 + 2] = k4.z; Ks[n * 33 + d4 + 3] = k4.w;
        float4 v4 = *(const float4*)(qkv + base + 1024);
        Vs[n][d4 + 0] = v4.x; Vs[n][d4 + 1] = v4.y;
        Vs[n][d4 + 2] = v4.z; Vs[n][d4 + 3] = v4.w;
    }
    {
        int bt = wb >> 6, wi = wb & 63, hb = wi >> 3, wk = wi & 7;
        for (int v = tid; v < 960; v += 256) {
            int dyp = v >> 6, jj = v & 63;
            float Dv = Dp[bt * 4096 + (((hb << 3) + (jj >> 3)) << 6) + (wk << 3) + (jj & 7)];
            float ang = (float)(dyp - 7) * Dv * RDC;
            float sn, cs; __sincosf(ang, &sn, &cs);
            csr[dyp][jj] = cs; ssr[dyp][jj] = sn;
        }
    }
    if (tid < 15) {
        arh[tid] = a_r[tid * NHd + h];
        brh[tid] = b_r[tid * NHd + h];
        int dx = tid - 7;
        int ip = dx < 0 ? dx + 15 : dx;
        float azf = (float)dx * AZC;
        float sn, cs; __sincosf(azf, &sn, &cs);
        phs[tid] = a_p[ip * NHd + h] * cs + b_p[ip * NHd + h] * sn;
    }
    __syncthreads();

    const int j = tid & 63, ig = tid >> 6;
    float acc[16];
    #pragma unroll
    for (int ii = 0; ii < 16; ii++) acc[ii] = 0.0f;
    #pragma unroll 8
    for (int d = 0; d < 32; d++) {
        float kv = Ks[j * 33 + d];
        #pragma unroll
        for (int ii = 0; ii < 16; ii++)
            acc[ii] += Qs[(ig * 16 + ii) * 33 + d] * kv;
    }
    const int yj = j >> 3, xjm = j & 7;
    #pragma unroll
    for (int ii = 0; ii < 16; ii++) {
        int i = ig * 16 + ii;
        int dy = (i >> 3) - yj;
        int dyp = dy + 7;
        int ir = dy < 0 ? dy + 15 : dy;
        int dxp = (i & 7) - xjm + 7;
        acc[ii] += phs[dxp] + arh[ir] * csr[dyp][j] + brh[ir] * ssr[dyp][j];
    }
    __syncthreads();
    float* Ss = QK;
    #pragma unroll
    for (int ii = 0; ii < 16; ii++) Ss[(ig * 16 + ii) * 65 + j] = acc[ii];
    __syncthreads();

    {
        int i = tid >> 2, p = tid & 3;
        float vals[16];
        float mx = -1e30f;
        #pragma unroll
        for (int u = 0; u < 16; u++) { vals[u] = Ss[i * 65 + p * 16 + u]; mx = fmaxf(mx, vals[u]); }
        mx = fmaxf(mx, __shfl_xor_sync(0xffffffffu, mx, 1));
        mx = fmaxf(mx, __shfl_xor_sync(0xffffffffu, mx, 2));
        float sm = 0.0f;
        #pragma unroll
        for (int u = 0; u < 16; u++) { vals[u] = __expf(vals[u] - mx); sm += vals[u]; }
        sm += __shfl_xor_sync(0xffffffffu, sm, 1);
        sm += __shfl_xor_sync(0xffffffffu, sm, 2);
        float inv = 1.0f / sm;
        #pragma unroll
        for (int u = 0; u < 16; u++) Ss[i * 65 + p * 16 + u] = vals[u] * inv;
    }
    __syncthreads();

    {
        int d = tid & 31, ig2 = tid >> 5;
        float acc2[8];
        #pragma unroll
        for (int u = 0; u < 8; u++) acc2[u] = 0.0f;
        #pragma unroll 4
        for (int m = 0; m < 64; m++) {
            float vv = Vs[m][d];
            #pragma unroll
            for (int u = 0; u < 8; u++)
                acc2[u] += Ss[(ig2 * 8 + u) * 65 + m] * vv;
        }
        #pragma unroll
        for (int u = 0; u < 8; u++) {
            int i = ig2 * 8 + u;
            int row = wb * 64 + i;
            size_t o = packed_off(row, h * 32 + d, Mrows);
            outh[o] = __float2half_rn(acc2[u]);
        }
    }
}

// ---------------- launch -------------------------------------------------
extern "C" void kernel_launch(void* const* d_in, const int* in_sizes, int n_in,
                              void* d_out, int out_size) {
    (void)in_sizes; (void)n_in; (void)out_size;
    const float* x      = (const float*)d_in[0];
    const float* D      = (const float*)d_in[1];
    const float* n1g    = (const float*)d_in[2];
    const float* n1b    = (const float*)d_in[3];
    const float* qkv_w  = (const float*)d_in[4];
    const float* qkv_b  = (const float*)d_in[5];
    const float* proj_w = (const float*)d_in[6];
    const float* proj_b = (const float*)d_in[7];
    const float* a_p    = (const float*)d_in[8];
    const float* b_p    = (const float*)d_in[9];
    const float* a_r    = (const float*)d_in[10];
    const float* b_r    = (const float*)d_in[11];
    const float* n2g    = (const float*)d_in[12];
    const float* n2b    = (const float*)d_in[13];
    const float* fc1_w  = (const float*)d_in[14];
    const float* fc1_b  = (const float*)d_in[15];
    const float* fc2_w  = (const float*)d_in[16];
    const float* fc2_b  = (const float*)d_in[17];
    float* out = (float*)d_out;

    __half *xw, *at, *xm, *hb;
    __half *wqh, *wql, *wph, *wpl, *w1h, *w1l, *w2h, *w2l;
    float *qkvb, *x2;
    cudaGetSymbolAddress((void**)&xw, g_xw);
    cudaGetSymbolAddress((void**)&at, g_at);
    cudaGetSymbolAddress((void**)&xm, g_xm);
    cudaGetSymbolAddress((void**)&hb, g_h);
    cudaGetSymbolAddress((void**)&wqh, g_wq_h); cudaGetSymbolAddress((void**)&wql, g_wq_l);
    cudaGetSymbolAddress((void**)&wph, g_wp_h); cudaGetSymbolAddress((void**)&wpl, g_wp_l);
    cudaGetSymbolAddress((void**)&w1h, g_w1_h); cudaGetSymbolAddress((void**)&w1l, g_w1_l);
    cudaGetSymbolAddress((void**)&w2h, g_w2_h); cudaGetSymbolAddress((void**)&w2l, g_w2_l);
    cudaGetSymbolAddress((void**)&qkvb, g_qkv); cudaGetSymbolAddress((void**)&x2, g_x2);

    cudaFuncSetAttribute(tgemm<EP_BIAS>, cudaFuncAttributeMaxDynamicSharedMemorySize, SMEM_TOT);
    cudaFuncSetAttribute(tgemm<EP_GELU>, cudaFuncAttributeMaxDynamicSharedMemorySize, SMEM_TOT);
    cudaFuncSetAttribute(tgemm<EP_PROJ>, cudaFuncAttributeMaxDynamicSharedMemorySize, SMEM_TOT);
    cudaFuncSetAttribute(tgemm<EP_ADD>,  cudaFuncAttributeMaxDynamicSharedMemorySize, SMEM_TOT);

    // weight conversions into packed layout
    cvt_w<<<(1536 * 512 / 8) / 256, 256>>>(qkv_w,  wqh, wql, 1536, 512);
    cvt_w<<<(512 * 512 / 8)  / 256, 256>>>(proj_w, wph, wpl, 512,  512);
    cvt_w<<<(2048 * 512 / 8) / 256, 256>>>(fc1_w,  w1h, w1l, 2048, 512);
    cvt_w<<<(512 * 2048 / 8) / 256, 256>>>(fc2_w,  w2h, w2l, 512,  2048);

    // 1) LN1 + window partition -> packed fp16
    ln_kernel<<<Mrows, 128>>>(x, n1g, n1b, xw, 1);
    // 2) QKV GEMM
    tgemm<EP_BIAS><<<dim3(1536 / 256, Mrows / 128), 256, SMEM_TOT>>>(
        512, 1536, xw, wqh, wql, qkv_b, nullptr, qkvb, nullptr);
    // 3) fused windowed attention -> packed fp16
    attn_kernel<<<dim3(1024, 16), 256>>>(qkvb, D, a_p, b_p, a_r, b_r, at);
    // 4) proj GEMM + window reverse + residual
    tgemm<EP_PROJ><<<dim3(512 / 256, Mrows / 128), 256, SMEM_TOT>>>(
        512, 512, at, wph, wpl, proj_b, x, x2, nullptr);
    // 5) LN2 -> packed fp16
    ln_kernel<<<Mrows, 128>>>(x2, n2g, n2b, xm, 0);
    // 6) fc1 + GELU -> packed fp16
    tgemm<EP_GELU><<<dim3(2048 / 256, Mrows / 128), 256, SMEM_TOT>>>(
        512, 2048, xm, w1h, w1l, fc1_b, nullptr, nullptr, hb);
    // 7) fc2 + residual -> output
    tgemm<EP_ADD><<<dim3(512 / 256, Mrows / 128), 256, SMEM_TOT>>>(
        2048, 512, hb, w2h, w2l, fc2_b, x2, out, nullptr);
}

// round 11
// speedup vs baseline: 5.5786x; 1.3808x over previous
#include <cuda_runtime.h>
#include <cuda_fp16.h>
#include <cstdint>

// ---------------- problem constants ----------------
#define Cdim  512
#define NHd   16
#define HDd   32
#define Ltok  4096
#define Mrows 65536
#define HIDd  2048

// ---------------- scratch (device globals) --------------------------------
// activations: single fp16, K-blocked pre-swizzled packed layout (packed_off)
__device__ __half g_xw[(size_t)Mrows * Cdim];
__device__ float  g_qkv[(size_t)Mrows * 3 * Cdim];
__device__ __half g_at[(size_t)Mrows * Cdim];
__device__ float  g_x2[(size_t)Mrows * Cdim];
__device__ __half g_xm[(size_t)Mrows * Cdim];
__device__ __half g_h [(size_t)Mrows * HIDd];
// weights: single fp16, packed layout
__device__ __half g_wq[1536 * 512];
__device__ __half g_wp[512 * 512];
__device__ __half g_w1[2048 * 512];
__device__ __half g_w2[512 * 2048];

// windowed row r -> (batch, natural token l)
__device__ __forceinline__ void win_to_nat(int r, int& bt, int& l) {
    int wb = r >> 6, n = r & 63;
    bt = wb >> 6;
    int wi = wb & 63;
    int hb = wi >> 3, wk = wi & 7;
    l = (((hb << 3) + (n >> 3)) << 6) + (wk << 3) + (n & 7);
}

// K-blocked packed layout with baked-in ldmatrix swizzle.
__device__ __forceinline__ size_t packed_off(int row, int k, int RowsTotal) {
    int kt = k >> 5;
    int ch = (k >> 3) & 3;
    int c7 = (((row & 1) << 2) | ch) ^ ((row >> 1) & 7);
    return (((size_t)kt * RowsTotal + (row & ~1)) << 5) + (c7 << 3) + (k & 7);
}

// ---------------- PTX helpers ---------------------------------------------
__device__ __forceinline__ uint32_t smem_u32(const void* p) {
    uint32_t a;
    asm("{ .reg .u64 t; cvta.to.shared.u64 t, %1; cvt.u32.u64 %0, t; }" : "=r"(a) : "l"(p));
    return a;
}
__device__ __forceinline__ void mbar_init(uint32_t m, uint32_t cnt) {
    asm volatile("mbarrier.init.shared.b64 [%0], %1;" :: "r"(m), "r"(cnt) : "memory");
}
__device__ __forceinline__ void mbar_wait(uint32_t m, uint32_t parity) {
    asm volatile(
        "{\n\t.reg .pred P;\n\t"
        "W_%=:\n\t"
        "mbarrier.try_wait.parity.acquire.cta.shared::cta.b64 P, [%0], %1, 0x989680;\n\t"
        "@P bra D_%=;\n\t"
        "bra W_%=;\n\t"
        "D_%=:\n\t}"
        :: "r"(m), "r"(parity) : "memory");
}
__device__ __forceinline__ void mbar_arrive(uint32_t m) {
    asm volatile("mbarrier.arrive.shared.b64 _, [%0];" :: "r"(m) : "memory");
}
__device__ __forceinline__ void mbar_expect_tx(uint32_t m, uint32_t bytes) {
    asm volatile("mbarrier.arrive.expect_tx.shared.b64 _, [%0], %1;"
                 :: "r"(m), "r"(bytes) : "memory");
}
__device__ __forceinline__ void bulk_g2s(uint32_t dst, const void* src,
                                         uint32_t bytes, uint32_t mbar) {
    asm volatile(
        "cp.async.bulk.shared::cluster.global.mbarrier::complete_tx::bytes [%0], [%1], %2, [%3];"
        :: "r"(dst), "l"(src), "r"(bytes), "r"(mbar) : "memory");
}

__device__ __forceinline__ uint32_t swz(uint32_t off) {
    return off ^ (((off >> 7) & 7) << 4);
}
__device__ __forceinline__ void ldmx4(uint32_t addr, uint32_t& r0, uint32_t& r1,
                                      uint32_t& r2, uint32_t& r3) {
    asm volatile("ldmatrix.sync.aligned.m8n8.x4.shared.b16 {%0,%1,%2,%3}, [%4];"
                 : "=r"(r0), "=r"(r1), "=r"(r2), "=r"(r3) : "r"(addr));
}
__device__ __forceinline__ void mma16816(float* c, const uint32_t* a, const uint32_t* b) {
    asm volatile(
        "mma.sync.aligned.m16n8k16.row.col.f32.f16.f16.f32 "
        "{%0,%1,%2,%3}, {%4,%5,%6,%7}, {%8,%9}, {%0,%1,%2,%3};"
        : "+f"(c[0]), "+f"(c[1]), "+f"(c[2]), "+f"(c[3])
        : "r"(a[0]), "r"(a[1]), "r"(a[2]), "r"(a[3]), "r"(b[0]), "r"(b[1]));
}

// ---------------- mma.sync GEMM, bulk-copy loaded, single fp16 pass -------
// C[M x Nout] = Act[M x K] * W[Nout x K]^T, fp16 inputs, fp32 accum.
// CTA: 128 act rows x 256 out cols, K-tile 32, 8 warps (2M x 4N), warp 64x64.
// 4-stage pipeline (structure identical to the R8/R9 passing kernels).
#define STG       24576          // A 8K | W 16K
#define NSTAGE    4
#define SMEM_TOT  (1024 + NSTAGE * STG)

#define EP_BIAS 0
#define EP_GELU 1
#define EP_PROJ 2
#define EP_ADD  3

__device__ __forceinline__ void issue_stage(
    uint32_t sbase, int kn, int b, int Nout, int bm0, int bn0,
    const __half* __restrict__ A, const __half* __restrict__ W)
{
    const uint32_t mbar = sbase + b * 8;
    const uint32_t sb = sbase + 1024 + b * STG;
    mbar_expect_tx(mbar, 24576u);
    const size_t aoff = ((size_t)kn * Mrows + bm0) << 6;   // bytes
    const size_t woff = ((size_t)kn * Nout + bn0) << 6;
    bulk_g2s(sb,        (const char*)A + aoff, 8192,  mbar);
    bulk_g2s(sb + 8192, (const char*)W + woff, 16384, mbar);
}

template<int EPI>
__global__ void __launch_bounds__(256, 1) tgemm(
    int K, int Nout,
    const __half* __restrict__ A, const __half* __restrict__ W,
    const float* __restrict__ bias, const float* __restrict__ res,
    float* __restrict__ outf, __half* __restrict__ outh)
{
    extern __shared__ char smem[];
    const uint32_t sbase = smem_u32(smem);
    const int tid  = threadIdx.x;
    const int bn0  = blockIdx.x * 256;
    const int bm0  = blockIdx.y * 128;
    const int warp = tid >> 5, lane = tid & 31;
    const int wm = (warp >> 2) * 64;
    const int wn = (warp & 3) * 64;

    // full barriers at sbase + b*8 (b<4), empty barriers at sbase + 32 + b*8
    if (tid == 0) {
        #pragma unroll
        for (int s = 0; s < NSTAGE; s++) {
            mbar_init(sbase + s * 8, 1);
            mbar_init(sbase + 32 + s * 8, 256);
        }
        asm volatile("fence.proxy.async.shared::cta;" ::: "memory");
    }
    __syncthreads();

    const int nk = K >> 5;
    if (tid == 0) {
        issue_stage(sbase, 0, 0, Nout, bm0, bn0, A, W);
        issue_stage(sbase, 1, 1, Nout, bm0, bn0, A, W);
        issue_stage(sbase, 2, 2, Nout, bm0, bn0, A, W);
        issue_stage(sbase, 3, 3, Nout, bm0, bn0, A, W);
    }

    float acc[4][8][4];
    #pragma unroll
    for (int mf = 0; mf < 4; mf++)
        #pragma unroll
        for (int nf = 0; nf < 8; nf++)
            #pragma unroll
            for (int u = 0; u < 4; u++) acc[mf][nf][u] = 0.0f;

    const int rA = wm + (lane & 15);
    const int rB = wn + (lane & 15);
    const int cb = lane >> 4;

    for (int kt = 0; kt < nk; kt++) {
        const int b = kt & 3;
        const int cyc = kt >> 2;
        mbar_wait(sbase + b * 8, cyc & 1);

        const uint32_t sg = sbase + 1024 + b * STG;
        const uint32_t at = sg;
        const uint32_t wt = sg + 8192;
        #pragma unroll
        for (int kf = 0; kf < 2; kf++) {
            const int ch = kf * 2 + cb;
            uint32_t a[4][4];
            #pragma unroll
            for (int mf = 0; mf < 4; mf++)
                ldmx4(at + swz((rA + mf * 16) * 64 + ch * 16),
                      a[mf][0], a[mf][1], a[mf][2], a[mf][3]);
            uint32_t b2[8][2];
            #pragma unroll
            for (int n2 = 0; n2 < 4; n2++) {
                uint32_t r0, r1, r2, r3;
                ldmx4(wt + swz((rB + n2 * 16) * 64 + ch * 16), r0, r1, r2, r3);
                b2[2 * n2][0] = r0; b2[2 * n2][1] = r2;
                b2[2 * n2 + 1][0] = r1; b2[2 * n2 + 1][1] = r3;
            }
            #pragma unroll
            for (int mf = 0; mf < 4; mf++)
                #pragma unroll
                for (int nf = 0; nf < 8; nf++)
                    mma16816(acc[mf][nf], a[mf], b2[nf]);
        }
        mbar_arrive(sbase + 32 + b * 8);
        if (tid == 0 && kt + NSTAGE < nk) {
            mbar_wait(sbase + 32 + b * 8, cyc & 1);
            issue_stage(sbase, kt + NSTAGE, b, Nout, bm0, bn0, A, W);
        }
    }

    // ---------------- epilogue ----------------
    const int g = lane >> 2, q = lane & 3;
    #pragma unroll
    for (int mf = 0; mf < 4; mf++) {
        const int row0 = bm0 + wm + mf * 16 + g;
        const int row1 = row0 + 8;
        size_t ob0, ob1;
        if (EPI == EP_PROJ) {
            int bt, l;
            win_to_nat(row0, bt, l); ob0 = ((size_t)bt * Ltok + l) * (size_t)Nout;
            win_to_nat(row1, bt, l); ob1 = ((size_t)bt * Ltok + l) * (size_t)Nout;
        } else {
            ob0 = (size_t)row0 * Nout;
            ob1 = (size_t)row1 * Nout;
        }
        #pragma unroll
        for (int nf = 0; nf < 8; nf++) {
            const int col = bn0 + wn + nf * 8 + q * 2;
            const float b0 = bias[col], b1 = bias[col + 1];
            float v00 = acc[mf][nf][0] + b0, v01 = acc[mf][nf][1] + b1;
            float v10 = acc[mf][nf][2] + b0, v11 = acc[mf][nf][3] + b1;
            if (EPI == EP_BIAS) {
                *(float2*)(outf + ob0 + col) = make_float2(v00, v01);
                *(float2*)(outf + ob1 + col) = make_float2(v10, v11);
            } else if (EPI == EP_GELU) {
                v00 = 0.5f * v00 * (1.0f + erff(v00 * 0.70710678118654752f));
                v01 = 0.5f * v01 * (1.0f + erff(v01 * 0.70710678118654752f));
                v10 = 0.5f * v10 * (1.0f + erff(v10 * 0.70710678118654752f));
                v11 = 0.5f * v11 * (1.0f + erff(v11 * 0.70710678118654752f));
                size_t p0 = packed_off(row0, col, Mrows);
                size_t p1 = packed_off(row1, col, Mrows);
                *(__half2*)(outh + p0) = __halves2half2(__float2half_rn(v00), __float2half_rn(v01));
                *(__half2*)(outh + p1) = __halves2half2(__float2half_rn(v10), __float2half_rn(v11));
            } else {  // EP_PROJ / EP_ADD: += residual
                float2 r0 = *(const float2*)(res + ob0 + col);
                float2 r1 = *(const float2*)(res + ob1 + col);
                *(float2*)(outf + ob0 + col) = make_float2(v00 + r0.x, v01 + r0.y);
                *(float2*)(outf + ob1 + col) = make_float2(v10 + r1.x, v11 + r1.y);
            }
        }
    }
}

// ---------------- fp32 -> fp16 weight conversion (packed) -----------------
__global__ __launch_bounds__(256) void cvt_w(
    const float* __restrict__ src, __half* __restrict__ dst, int Rows, int K)
{
    int i = blockIdx.x * 256 + threadIdx.x;   // 16B-chunk id
    int cpr = K >> 3;
    int n = i / cpr;
    int kc = (i - n * cpr) << 3;
    const float4* s = (const float4*)(src + (size_t)n * K + kc);
    float4 v0 = s[0], v1 = s[1];
    float vv[8] = { v0.x, v0.y, v0.z, v0.w, v1.x, v1.y, v1.z, v1.w };
    __half h[8];
    #pragma unroll
    for (int u = 0; u < 8; u++) h[u] = __float2half_rn(vv[u]);
    size_t o = packed_off(n, kc, Rows);
    *(uint4*)(dst + o) = *(uint4*)h;
}

// ---------------- LayerNorm -> fp16 (packed) ------------------------------
__global__ __launch_bounds__(128) void ln_kernel(
    const float* __restrict__ x, const float* __restrict__ g,
    const float* __restrict__ b, __half* __restrict__ outh, int windowed)
{
    int r = blockIdx.x;
    size_t ibase;
    if (windowed) {
        int bt, l; win_to_nat(r, bt, l);
        ibase = ((size_t)bt * Ltok + l) * Cdim;
    } else {
        ibase = (size_t)r * Cdim;
    }
    int t = threadIdx.x;
    float4 v = *(const float4*)(x + ibase + t * 4);
    float s  = v.x + v.y + v.z + v.w;
    float sq = v.x*v.x + v.y*v.y + v.z*v.z + v.w*v.w;
    #pragma unroll
    for (int off = 16; off; off >>= 1) {
        s  += __shfl_xor_sync(0xffffffffu, s,  off);
        sq += __shfl_xor_sync(0xffffffffu, sq, off);
    }
    __shared__ float ws[4], wq[4];
    int wid = t >> 5, lane = t & 31;
    if (lane == 0) { ws[wid] = s; wq[wid] = sq; }
    __syncthreads();
    s  = ws[0] + ws[1] + ws[2] + ws[3];
    sq = wq[0] + wq[1] + wq[2] + wq[3];
    float mean = s * (1.0f / 512.0f);
    float var  = sq * (1.0f / 512.0f) - mean * mean;
    float rstd = rsqrtf(var + 1e-5f);
    float4 gg = *(const float4*)(g + t * 4);
    float4 bb = *(const float4*)(b + t * 4);
    __half hv[4];
    hv[0] = __float2half_rn((v.x - mean) * rstd * gg.x + bb.x);
    hv[1] = __float2half_rn((v.y - mean) * rstd * gg.y + bb.y);
    hv[2] = __float2half_rn((v.z - mean) * rstd * gg.z + bb.z);
    hv[3] = __float2half_rn((v.w - mean) * rstd * gg.w + bb.w);
    size_t o = packed_off(r, t * 4, Mrows);
    *(uint2*)(outh + o) = *(uint2*)hv;
}

// ---------------- fused windowed attention (fp16 packed out) --------------
#define QSCALE 0.17677669529663687f
#define AZC    0.09817477042468103f
#define RDC    0.02454369260617026f

__global__ __launch_bounds__(256) void attn_kernel(
    const float* __restrict__ qkv, const float* __restrict__ Dp,
    const float* __restrict__ a_p, const float* __restrict__ b_p,
    const float* __restrict__ a_r, const float* __restrict__ b_r,
    __half* __restrict__ outh)
{
    __shared__ float QK[4224];
    __shared__ float Vs[64][33];
    __shared__ float csr[15][64];
    __shared__ float ssr[15][64];
    __shared__ float arh[15], brh[15], phs[15];

    const int wb  = blockIdx.x;
    const int h   = blockIdx.y;
    const int tid = threadIdx.x;
    float* Qs = QK;
    float* Ks = QK + 64 * 33;

    for (int v = tid; v < 512; v += 256) {
        int n = v >> 3, d4 = (v & 7) << 2;
        size_t base = ((size_t)(wb * 64 + n)) * 1536 + h * 32 + d4;
        float4 q4 = *(const float4*)(qkv + base);
        Qs[n * 33 + d4 + 0] = q4.x * QSCALE;
        Qs[n * 33 + d4 + 1] = q4.y * QSCALE;
        Qs[n * 33 + d4 + 2] = q4.z * QSCALE;
        Qs[n * 33 + d4 + 3] = q4.w * QSCALE;
        float4 k4 = *(const float4*)(qkv + base + 512);
        Ks[n * 33 + d4 + 0] = k4.x; Ks[n * 33 + d4 + 1] = k4.y;
        Ks[n * 33 + d4 + 2] = k4.z; Ks[n * 33 + d4 + 3] = k4.w;
        float4 v4 = *(const float4*)(qkv + base + 1024);
        Vs[n][d4 + 0] = v4.x; Vs[n][d4 + 1] = v4.y;
        Vs[n][d4 + 2] = v4.z; Vs[n][d4 + 3] = v4.w;
    }
    {
        int bt = wb >> 6, wi = wb & 63, hb = wi >> 3, wk = wi & 7;
        for (int v = tid; v < 960; v += 256) {
            int dyp = v >> 6, jj = v & 63;
            float Dv = Dp[bt * 4096 + (((hb << 3) + (jj >> 3)) << 6) + (wk << 3) + (jj & 7)];
            float ang = (float)(dyp - 7) * Dv * RDC;
            float sn, cs; __sincosf(ang, &sn, &cs);
            csr[dyp][jj] = cs; ssr[dyp][jj] = sn;
        }
    }
    if (tid < 15) {
        arh[tid] = a_r[tid * NHd + h];
        brh[tid] = b_r[tid * NHd + h];
        int dx = tid - 7;
        int ip = dx < 0 ? dx + 15 : dx;
        float azf = (float)dx * AZC;
        float sn, cs; __sincosf(azf, &sn, &cs);
        phs[tid] = a_p[ip * NHd + h] * cs + b_p[ip * NHd + h] * sn;
    }
    __syncthreads();

    const int j = tid & 63, ig = tid >> 6;
    float acc[16];
    #pragma unroll
    for (int ii = 0; ii < 16; ii++) acc[ii] = 0.0f;
    #pragma unroll 8
    for (int d = 0; d < 32; d++) {
        float kv = Ks[j * 33 + d];
        #pragma unroll
        for (int ii = 0; ii < 16; ii++)
            acc[ii] += Qs[(ig * 16 + ii) * 33 + d] * kv;
    }
    const int yj = j >> 3, xjm = j & 7;
    #pragma unroll
    for (int ii = 0; ii < 16; ii++) {
        int i = ig * 16 + ii;
        int dy = (i >> 3) - yj;
        int dyp = dy + 7;
        int ir = dy < 0 ? dy + 15 : dy;
        int dxp = (i & 7) - xjm + 7;
        acc[ii] += phs[dxp] + arh[ir] * csr[dyp][j] + brh[ir] * ssr[dyp][j];
    }
    __syncthreads();
    float* Ss = QK;
    #pragma unroll
    for (int ii = 0; ii < 16; ii++) Ss[(ig * 16 + ii) * 65 + j] = acc[ii];
    __syncthreads();

    {
        int i = tid >> 2, p = tid & 3;
        float vals[16];
        float mx = -1e30f;
        #pragma unroll
        for (int u = 0; u < 16; u++) { vals[u] = Ss[i * 65 + p * 16 + u]; mx = fmaxf(mx, vals[u]); }
        mx = fmaxf(mx, __shfl_xor_sync(0xffffffffu, mx, 1));
        mx = fmaxf(mx, __shfl_xor_sync(0xffffffffu, mx, 2));
        float sm = 0.0f;
        #pragma unroll
        for (int u = 0; u < 16; u++) { vals[u] = __expf(vals[u] - mx); sm += vals[u]; }
        sm += __shfl_xor_sync(0xffffffffu, sm, 1);
        sm += __shfl_xor_sync(0xffffffffu, sm, 2);
        float inv = 1.0f / sm;
        #pragma unroll
        for (int u = 0; u < 16; u++) Ss[i * 65 + p * 16 + u] = vals[u] * inv;
    }
    __syncthreads();

    {
        int d = tid & 31, ig2 = tid >> 5;
        float acc2[8];
        #pragma unroll
        for (int u = 0; u < 8; u++) acc2[u] = 0.0f;
        #pragma unroll 4
        for (int m = 0; m < 64; m++) {
            float vv = Vs[m][d];
            #pragma unroll
            for (int u = 0; u < 8; u++)
                acc2[u] += Ss[(ig2 * 8 + u) * 65 + m] * vv;
        }
        #pragma unroll
        for (int u = 0; u < 8; u++) {
            int i = ig2 * 8 + u;
            int row = wb * 64 + i;
            size_t o = packed_off(row, h * 32 + d, Mrows);
            outh[o] = __float2half_rn(acc2[u]);
        }
    }
}

// ---------------- launch -------------------------------------------------
extern "C" void kernel_launch(void* const* d_in, const int* in_sizes, int n_in,
                              void* d_out, int out_size) {
    (void)in_sizes; (void)n_in; (void)out_size;
    const float* x      = (const float*)d_in[0];
    const float* D      = (const float*)d_in[1];
    const float* n1g    = (const float*)d_in[2];
    const float* n1b    = (const float*)d_in[3];
    const float* qkv_w  = (const float*)d_in[4];
    const float* qkv_b  = (const float*)d_in[5];
    const float* proj_w = (const float*)d_in[6];
    const float* proj_b = (const float*)d_in[7];
    const float* a_p    = (const float*)d_in[8];
    const float* b_p    = (const float*)d_in[9];
    const float* a_r    = (const float*)d_in[10];
    const float* b_r    = (const float*)d_in[11];
    const float* n2g    = (const float*)d_in[12];
    const float* n2b    = (const float*)d_in[13];
    const float* fc1_w  = (const float*)d_in[14];
    const float* fc1_b  = (const float*)d_in[15];
    const float* fc2_w  = (const float*)d_in[16];
    const float* fc2_b  = (const float*)d_in[17];
    float* out = (float*)d_out;

    __half *xw, *at, *xm, *hb, *wq, *wp, *w1, *w2;
    float *qkvb, *x2;
    cudaGetSymbolAddress((void**)&xw, g_xw);
    cudaGetSymbolAddress((void**)&at, g_at);
    cudaGetSymbolAddress((void**)&xm, g_xm);
    cudaGetSymbolAddress((void**)&hb, g_h);
    cudaGetSymbolAddress((void**)&wq, g_wq);
    cudaGetSymbolAddress((void**)&wp, g_wp);
    cudaGetSymbolAddress((void**)&w1, g_w1);
    cudaGetSymbolAddress((void**)&w2, g_w2);
    cudaGetSymbolAddress((void**)&qkvb, g_qkv);
    cudaGetSymbolAddress((void**)&x2, g_x2);

    cudaFuncSetAttribute(tgemm<EP_BIAS>, cudaFuncAttributeMaxDynamicSharedMemorySize, SMEM_TOT);
    cudaFuncSetAttribute(tgemm<EP_GELU>, cudaFuncAttributeMaxDynamicSharedMemorySize, SMEM_TOT);
    cudaFuncSetAttribute(tgemm<EP_PROJ>, cudaFuncAttributeMaxDynamicSharedMemorySize, SMEM_TOT);
    cudaFuncSetAttribute(tgemm<EP_ADD>,  cudaFuncAttributeMaxDynamicSharedMemorySize, SMEM_TOT);

    // weight conversions into packed layout
    cvt_w<<<(1536 * 512 / 8) / 256, 256>>>(qkv_w,  wq, 1536, 512);
    cvt_w<<<(512 * 512 / 8)  / 256, 256>>>(proj_w, wp, 512,  512);
    cvt_w<<<(2048 * 512 / 8) / 256, 256>>>(fc1_w,  w1, 2048, 512);
    cvt_w<<<(512 * 2048 / 8) / 256, 256>>>(fc2_w,  w2, 512,  2048);

    // 1) LN1 + window partition -> packed fp16
    ln_kernel<<<Mrows, 128>>>(x, n1g, n1b, xw, 1);
    // 2) QKV GEMM
    tgemm<EP_BIAS><<<dim3(1536 / 256, Mrows / 128), 256, SMEM_TOT>>>(
        512, 1536, xw, wq, qkv_b, nullptr, qkvb, nullptr);
    // 3) fused windowed attention -> packed fp16
    attn_kernel<<<dim3(1024, 16), 256>>>(qkvb, D, a_p, b_p, a_r, b_r, at);
    // 4) proj GEMM + window reverse + residual
    tgemm<EP_PROJ><<<dim3(512 / 256, Mrows / 128), 256, SMEM_TOT>>>(
        512, 512, at, wp, proj_b, x, x2, nullptr);
    // 5) LN2 -> packed fp16
    ln_kernel<<<Mrows, 128>>>(x2, n2g, n2b, xm, 0);
    // 6) fc1 + GELU -> packed fp16
    tgemm<EP_GELU><<<dim3(2048 / 256, Mrows / 128), 256, SMEM_TOT>>>(
        512, 2048, xm, w1, fc1_b, nullptr, nullptr, hb);
    // 7) fc2 + residual -> output
    tgemm<EP_ADD><<<dim3(512 / 256, Mrows / 128), 256, SMEM_TOT>>>(
        2048, 512, hb, w2, fc2_b, x2, out, nullptr);
}

// round 12
// speedup vs baseline: 5.6634x; 1.0152x over previous
#include <cuda_runtime.h>
#include <cuda_fp16.h>
#include <cstdint>

// ---------------- problem constants ----------------
#define Cdim  512
#define NHd   16
#define HDd   32
#define Ltok  4096
#define Mrows 65536
#define HIDd  2048

// ---------------- scratch (device globals) --------------------------------
__device__ __half g_xw[(size_t)Mrows * Cdim];       // packed layout
__device__ __half g_qkvh[(size_t)Mrows * 3 * Cdim]; // natural layout fp16
__device__ __half g_at[(size_t)Mrows * Cdim];       // packed layout
__device__ float  g_x2[(size_t)Mrows * Cdim];
__device__ __half g_xm[(size_t)Mrows * Cdim];       // packed layout
__device__ __half g_h [(size_t)Mrows * HIDd];       // packed layout
__device__ __half g_wq[1536 * 512];
__device__ __half g_wp[512 * 512];
__device__ __half g_w1[2048 * 512];
__device__ __half g_w2[512 * 2048];

// windowed row r -> (batch, natural token l)
__device__ __forceinline__ void win_to_nat(int r, int& bt, int& l) {
    int wb = r >> 6, n = r & 63;
    bt = wb >> 6;
    int wi = wb & 63;
    int hb = wi >> 3, wk = wi & 7;
    l = (((hb << 3) + (n >> 3)) << 6) + (wk << 3) + (n & 7);
}

// K-blocked packed layout with baked-in ldmatrix swizzle.
__device__ __forceinline__ size_t packed_off(int row, int k, int RowsTotal) {
    int kt = k >> 5;
    int ch = (k >> 3) & 3;
    int c7 = (((row & 1) << 2) | ch) ^ ((row >> 1) & 7);
    return (((size_t)kt * RowsTotal + (row & ~1)) << 5) + (c7 << 3) + (k & 7);
}

// ---------------- PTX helpers ---------------------------------------------
__device__ __forceinline__ uint32_t smem_u32(const void* p) {
    uint32_t a;
    asm("{ .reg .u64 t; cvta.to.shared.u64 t, %1; cvt.u32.u64 %0, t; }" : "=r"(a) : "l"(p));
    return a;
}
__device__ __forceinline__ void mbar_init(uint32_t m, uint32_t cnt) {
    asm volatile("mbarrier.init.shared.b64 [%0], %1;" :: "r"(m), "r"(cnt) : "memory");
}
__device__ __forceinline__ void mbar_wait(uint32_t m, uint32_t parity) {
    asm volatile(
        "{\n\t.reg .pred P;\n\t"
        "W_%=:\n\t"
        "mbarrier.try_wait.parity.acquire.cta.shared::cta.b64 P, [%0], %1, 0x989680;\n\t"
        "@P bra D_%=;\n\t"
        "bra W_%=;\n\t"
        "D_%=:\n\t}"
        :: "r"(m), "r"(parity) : "memory");
}
__device__ __forceinline__ void mbar_arrive(uint32_t m) {
    asm volatile("mbarrier.arrive.shared.b64 _, [%0];" :: "r"(m) : "memory");
}
__device__ __forceinline__ void mbar_expect_tx(uint32_t m, uint32_t bytes) {
    asm volatile("mbarrier.arrive.expect_tx.shared.b64 _, [%0], %1;"
                 :: "r"(m), "r"(bytes) : "memory");
}
__device__ __forceinline__ void bulk_g2s(uint32_t dst, const void* src,
                                         uint32_t bytes, uint32_t mbar) {
    asm volatile(
        "cp.async.bulk.shared::cluster.global.mbarrier::complete_tx::bytes [%0], [%1], %2, [%3];"
        :: "r"(dst), "l"(src), "r"(bytes), "r"(mbar) : "memory");
}

__device__ __forceinline__ uint32_t swz(uint32_t off) {
    return off ^ (((off >> 7) & 7) << 4);
}
__device__ __forceinline__ void ldmx4(uint32_t addr, uint32_t& r0, uint32_t& r1,
                                      uint32_t& r2, uint32_t& r3) {
    asm volatile("ldmatrix.sync.aligned.m8n8.x4.shared.b16 {%0,%1,%2,%3}, [%4];"
                 : "=r"(r0), "=r"(r1), "=r"(r2), "=r"(r3) : "r"(addr));
}
__device__ __forceinline__ void mma16816(float* c, const uint32_t* a, const uint32_t* b) {
    asm volatile(
        "mma.sync.aligned.m16n8k16.row.col.f32.f16.f16.f32 "
        "{%0,%1,%2,%3}, {%4,%5,%6,%7}, {%8,%9}, {%0,%1,%2,%3};"
        : "+f"(c[0]), "+f"(c[1]), "+f"(c[2]), "+f"(c[3])
        : "r"(a[0]), "r"(a[1]), "r"(a[2]), "r"(a[3]), "r"(b[0]), "r"(b[1]));
}

// ---------------- mma.sync GEMM, bulk-copy loaded, single fp16 pass -------
// CTA: 128 act rows x 256 out cols, K-tile 32, 8 warps (2M x 4N), warp 64x64.
#define STG       24576          // A 8K | W 16K
#define NSTAGE    4
#define SMEM_TOT  (1024 + NSTAGE * STG)

#define EP_BIAS 0
#define EP_GELU 1
#define EP_PROJ 2
#define EP_ADD  3

__device__ __forceinline__ void issue_stage(
    uint32_t sbase, int kn, int b, int Nout, int bm0, int bn0,
    const __half* __restrict__ A, const __half* __restrict__ W)
{
    const uint32_t mbar = sbase + b * 8;
    const uint32_t sb = sbase + 1024 + b * STG;
    mbar_expect_tx(mbar, 24576u);
    const size_t aoff = ((size_t)kn * Mrows + bm0) << 6;   // bytes
    const size_t woff = ((size_t)kn * Nout + bn0) << 6;
    bulk_g2s(sb,        (const char*)A + aoff, 8192,  mbar);
    bulk_g2s(sb + 8192, (const char*)W + woff, 16384, mbar);
}

template<int EPI>
__global__ void __launch_bounds__(256, 1) tgemm(
    int K, int Nout,
    const __half* __restrict__ A, const __half* __restrict__ W,
    const float* __restrict__ bias, const float* __restrict__ res,
    float* __restrict__ outf, __half* __restrict__ outh)
{
    extern __shared__ char smem[];
    const uint32_t sbase = smem_u32(smem);
    const int tid  = threadIdx.x;
    const int bn0  = blockIdx.x * 256;
    const int bm0  = blockIdx.y * 128;
    const int warp = tid >> 5, lane = tid & 31;
    const int wm = (warp >> 2) * 64;
    const int wn = (warp & 3) * 64;

    if (tid == 0) {
        #pragma unroll
        for (int s = 0; s < NSTAGE; s++) {
            mbar_init(sbase + s * 8, 1);
            mbar_init(sbase + 32 + s * 8, 256);
        }
        asm volatile("fence.proxy.async.shared::cta;" ::: "memory");
    }
    __syncthreads();

    const int nk = K >> 5;
    if (tid == 0) {
        issue_stage(sbase, 0, 0, Nout, bm0, bn0, A, W);
        issue_stage(sbase, 1, 1, Nout, bm0, bn0, A, W);
        issue_stage(sbase, 2, 2, Nout, bm0, bn0, A, W);
        issue_stage(sbase, 3, 3, Nout, bm0, bn0, A, W);
    }

    float acc[4][8][4];
    #pragma unroll
    for (int mf = 0; mf < 4; mf++)
        #pragma unroll
        for (int nf = 0; nf < 8; nf++)
            #pragma unroll
            for (int u = 0; u < 4; u++) acc[mf][nf][u] = 0.0f;

    const int rA = wm + (lane & 15);
    const int rB = wn + (lane & 15);
    const int cb = lane >> 4;

    for (int kt = 0; kt < nk; kt++) {
        const int b = kt & 3;
        const int cyc = kt >> 2;
        mbar_wait(sbase + b * 8, cyc & 1);

        const uint32_t sg = sbase + 1024 + b * STG;
        const uint32_t at = sg;
        const uint32_t wt = sg + 8192;
        #pragma unroll
        for (int kf = 0; kf < 2; kf++) {
            const int ch = kf * 2 + cb;
            uint32_t a[4][4];
            #pragma unroll
            for (int mf = 0; mf < 4; mf++)
                ldmx4(at + swz((rA + mf * 16) * 64 + ch * 16),
                      a[mf][0], a[mf][1], a[mf][2], a[mf][3]);
            uint32_t b2[8][2];
            #pragma unroll
            for (int n2 = 0; n2 < 4; n2++) {
                uint32_t r0, r1, r2, r3;
                ldmx4(wt + swz((rB + n2 * 16) * 64 + ch * 16), r0, r1, r2, r3);
                b2[2 * n2][0] = r0; b2[2 * n2][1] = r2;
                b2[2 * n2 + 1][0] = r1; b2[2 * n2 + 1][1] = r3;
            }
            #pragma unroll
            for (int mf = 0; mf < 4; mf++)
                #pragma unroll
                for (int nf = 0; nf < 8; nf++)
                    mma16816(acc[mf][nf], a[mf], b2[nf]);
        }
        mbar_arrive(sbase + 32 + b * 8);
        if (tid == 0 && kt + NSTAGE < nk) {
            mbar_wait(sbase + 32 + b * 8, cyc & 1);
            issue_stage(sbase, kt + NSTAGE, b, Nout, bm0, bn0, A, W);
        }
    }

    // ---------------- epilogue ----------------
    const int g = lane >> 2, q = lane & 3;
    #pragma unroll
    for (int mf = 0; mf < 4; mf++) {
        const int row0 = bm0 + wm + mf * 16 + g;
        const int row1 = row0 + 8;
        size_t ob0, ob1;
        if (EPI == EP_PROJ) {
            int bt, l;
            win_to_nat(row0, bt, l); ob0 = ((size_t)bt * Ltok + l) * (size_t)Nout;
            win_to_nat(row1, bt, l); ob1 = ((size_t)bt * Ltok + l) * (size_t)Nout;
        } else {
            ob0 = (size_t)row0 * Nout;
            ob1 = (size_t)row1 * Nout;
        }
        #pragma unroll
        for (int nf = 0; nf < 8; nf++) {
            const int col = bn0 + wn + nf * 8 + q * 2;
            const float b0 = bias[col], b1 = bias[col + 1];
            float v00 = acc[mf][nf][0] + b0, v01 = acc[mf][nf][1] + b1;
            float v10 = acc[mf][nf][2] + b0, v11 = acc[mf][nf][3] + b1;
            if (EPI == EP_BIAS) {
                // qkv buffer: fp16, natural layout
                *(__half2*)(outh + ob0 + col) = __halves2half2(__float2half_rn(v00), __float2half_rn(v01));
                *(__half2*)(outh + ob1 + col) = __halves2half2(__float2half_rn(v10), __float2half_rn(v11));
            } else if (EPI == EP_GELU) {
                v00 = 0.5f * v00 * (1.0f + erff(v00 * 0.70710678118654752f));
                v01 = 0.5f * v01 * (1.0f + erff(v01 * 0.70710678118654752f));
                v10 = 0.5f * v10 * (1.0f + erff(v10 * 0.70710678118654752f));
                v11 = 0.5f * v11 * (1.0f + erff(v11 * 0.70710678118654752f));
                size_t p0 = packed_off(row0, col, Mrows);
                size_t p1 = packed_off(row1, col, Mrows);
                *(__half2*)(outh + p0) = __halves2half2(__float2half_rn(v00), __float2half_rn(v01));
                *(__half2*)(outh + p1) = __halves2half2(__float2half_rn(v10), __float2half_rn(v11));
            } else {  // EP_PROJ / EP_ADD: += residual
                float2 r0 = *(const float2*)(res + ob0 + col);
                float2 r1 = *(const float2*)(res + ob1 + col);
                *(float2*)(outf + ob0 + col) = make_float2(v00 + r0.x, v01 + r0.y);
                *(float2*)(outf + ob1 + col) = make_float2(v10 + r1.x, v11 + r1.y);
            }
        }
    }
}

// ---------------- fp32 -> fp16 weight conversion (packed) -----------------
__global__ __launch_bounds__(256) void cvt_w(
    const float* __restrict__ src, __half* __restrict__ dst, int Rows, int K)
{
    int i = blockIdx.x * 256 + threadIdx.x;   // 16B-chunk id
    int cpr = K >> 3;
    int n = i / cpr;
    int kc = (i - n * cpr) << 3;
    const float4* s = (const float4*)(src + (size_t)n * K + kc);
    float4 v0 = s[0], v1 = s[1];
    float vv[8] = { v0.x, v0.y, v0.z, v0.w, v1.x, v1.y, v1.z, v1.w };
    __half h[8];
    #pragma unroll
    for (int u = 0; u < 8; u++) h[u] = __float2half_rn(vv[u]);
    size_t o = packed_off(n, kc, Rows);
    *(uint4*)(dst + o) = *(uint4*)h;
}

// ---------------- LayerNorm: warp-per-row -> fp16 packed ------------------
__global__ __launch_bounds__(256) void ln_kernel(
    const float* __restrict__ x, const float* __restrict__ g,
    const float* __restrict__ b, __half* __restrict__ outh, int windowed)
{
    const int warp = threadIdx.x >> 5, lane = threadIdx.x & 31;
    const int r = blockIdx.x * 8 + warp;
    size_t ibase;
    if (windowed) {
        int bt, l; win_to_nat(r, bt, l);
        ibase = ((size_t)bt * Ltok + l) * Cdim;
    } else {
        ibase = (size_t)r * Cdim;
    }
    float4 v[4];
    float s = 0.0f, sq = 0.0f;
    #pragma unroll
    for (int i = 0; i < 4; i++) {
        v[i] = *(const float4*)(x + ibase + i * 128 + lane * 4);
        s  += v[i].x + v[i].y + v[i].z + v[i].w;
        sq += v[i].x*v[i].x + v[i].y*v[i].y + v[i].z*v[i].z + v[i].w*v[i].w;
    }
    #pragma unroll
    for (int off = 16; off; off >>= 1) {
        s  += __shfl_xor_sync(0xffffffffu, s,  off);
        sq += __shfl_xor_sync(0xffffffffu, sq, off);
    }
    const float mean = s * (1.0f / 512.0f);
    const float var  = sq * (1.0f / 512.0f) - mean * mean;
    const float rstd = rsqrtf(var + 1e-5f);
    #pragma unroll
    for (int i = 0; i < 4; i++) {
        const int col = i * 128 + lane * 4;
        float4 gg = *(const float4*)(g + col);
        float4 bb = *(const float4*)(b + col);
        __half hv[4];
        hv[0] = __float2half_rn((v[i].x - mean) * rstd * gg.x + bb.x);
        hv[1] = __float2half_rn((v[i].y - mean) * rstd * gg.y + bb.y);
        hv[2] = __float2half_rn((v[i].z - mean) * rstd * gg.z + bb.z);
        hv[3] = __float2half_rn((v[i].w - mean) * rstd * gg.w + bb.w);
        *(uint2*)(outh + packed_off(r, col, Mrows)) = *(uint2*)hv;
    }
}

// ---------------- fused windowed attention (fp16 in, fp16 packed out) -----
#define QSCALE 0.17677669529663687f
#define AZC    0.09817477042468103f
#define RDC    0.02454369260617026f

__global__ __launch_bounds__(256) void attn_kernel(
    const __half* __restrict__ qkv, const float* __restrict__ Dp,
    const float* __restrict__ a_p, const float* __restrict__ b_p,
    const float* __restrict__ a_r, const float* __restrict__ b_r,
    __half* __restrict__ outh)
{
    __shared__ float QK[4224];
    __shared__ float Vs[64][33];
    __shared__ float csr[15][64];
    __shared__ float ssr[15][64];
    __shared__ float arh[15], brh[15], phs[15];

    const int wb  = blockIdx.x;
    const int h   = blockIdx.y;
    const int tid = threadIdx.x;
    float* Qs = QK;
    float* Ks = QK + 64 * 33;

    // load Q,K,V fp16 -> fp32 smem. thread: row n = tid>>2, 8-elem chunk c = tid&3
    {
        const int n = tid >> 2, c = tid & 3;
        const size_t base = ((size_t)(wb * 64 + n)) * 1536 + h * 32 + c * 8;
        uint4 qr = *(const uint4*)(qkv + base);
        uint4 kr = *(const uint4*)(qkv + base + 512);
        uint4 vr = *(const uint4*)(qkv + base + 1024);
        const __half2* qh = (const __half2*)&qr;
        const __half2* kh = (const __half2*)&kr;
        const __half2* vh = (const __half2*)&vr;
        #pragma unroll
        for (int j = 0; j < 4; j++) {
            float2 qf = __half22float2(qh[j]);
            float2 kf = __half22float2(kh[j]);
            float2 vf = __half22float2(vh[j]);
            int d = c * 8 + j * 2;
            Qs[n * 33 + d]     = qf.x * QSCALE;
            Qs[n * 33 + d + 1] = qf.y * QSCALE;
            Ks[n * 33 + d]     = kf.x;
            Ks[n * 33 + d + 1] = kf.y;
            Vs[n][d]     = vf.x;
            Vs[n][d + 1] = vf.y;
        }
    }
    {
        int bt = wb >> 6, wi = wb & 63, hb = wi >> 3, wk = wi & 7;
        for (int v = tid; v < 960; v += 256) {
            int dyp = v >> 6, jj = v & 63;
            float Dv = Dp[bt * 4096 + (((hb << 3) + (jj >> 3)) << 6) + (wk << 3) + (jj & 7)];
            float ang = (float)(dyp - 7) * Dv * RDC;
            float sn, cs; __sincosf(ang, &sn, &cs);
            csr[dyp][jj] = cs; ssr[dyp][jj] = sn;
        }
    }
    if (tid < 15) {
        arh[tid] = a_r[tid * NHd + h];
        brh[tid] = b_r[tid * NHd + h];
        int dx = tid - 7;
        int ip = dx < 0 ? dx + 15 : dx;
        float azf = (float)dx * AZC;
        float sn, cs; __sincosf(azf, &sn, &cs);
        phs[tid] = a_p[ip * NHd + h] * cs + b_p[ip * NHd + h] * sn;
    }
    __syncthreads();

    const int j = tid & 63, ig = tid >> 6;
    float acc[16];
    #pragma unroll
    for (int ii = 0; ii < 16; ii++) acc[ii] = 0.0f;
    #pragma unroll 8
    for (int d = 0; d < 32; d++) {
        float kv = Ks[j * 33 + d];
        #pragma unroll
        for (int ii = 0; ii < 16; ii++)
            acc[ii] += Qs[(ig * 16 + ii) * 33 + d] * kv;
    }
    const int yj = j >> 3, xjm = j & 7;
    #pragma unroll
    for (int ii = 0; ii < 16; ii++) {
        int i = ig * 16 + ii;
        int dy = (i >> 3) - yj;
        int dyp = dy + 7;
        int ir = dy < 0 ? dy + 15 : dy;
        int dxp = (i & 7) - xjm + 7;
        acc[ii] += phs[dxp] + arh[ir] * csr[dyp][j] + brh[ir] * ssr[dyp][j];
    }
    __syncthreads();
    float* Ss = QK;
    #pragma unroll
    for (int ii = 0; ii < 16; ii++) Ss[(ig * 16 + ii) * 65 + j] = acc[ii];
    __syncthreads();

    {
        int i = tid >> 2, p = tid & 3;
        float vals[16];
        float mx = -1e30f;
        #pragma unroll
        for (int u = 0; u < 16; u++) { vals[u] = Ss[i * 65 + p * 16 + u]; mx = fmaxf(mx, vals[u]); }
        mx = fmaxf(mx, __shfl_xor_sync(0xffffffffu, mx, 1));
        mx = fmaxf(mx, __shfl_xor_sync(0xffffffffu, mx, 2));
        float sm = 0.0f;
        #pragma unroll
        for (int u = 0; u < 16; u++) { vals[u] = __expf(vals[u] - mx); sm += vals[u]; }
        sm += __shfl_xor_sync(0xffffffffu, sm, 1);
        sm += __shfl_xor_sync(0xffffffffu, sm, 2);
        float inv = 1.0f / sm;
        #pragma unroll
        for (int u = 0; u < 16; u++) Ss[i * 65 + p * 16 + u] = vals[u] * inv;
    }
    __syncthreads();

    {
        int d = tid & 31, ig2 = tid >> 5;
        float acc2[8];
        #pragma unroll
        for (int u = 0; u < 8; u++) acc2[u] = 0.0f;
        #pragma unroll 4
        for (int m = 0; m < 64; m++) {
            float vv = Vs[m][d];
            #pragma unroll
            for (int u = 0; u < 8; u++)
                acc2[u] += Ss[(ig2 * 8 + u) * 65 + m] * vv;
        }
        #pragma unroll
        for (int u = 0; u < 8; u++) {
            int i = ig2 * 8 + u;
            int row = wb * 64 + i;
            size_t o = packed_off(row, h * 32 + d, Mrows);
            outh[o] = __float2half_rn(acc2[u]);
        }
    }
}

// ---------------- launch -------------------------------------------------
extern "C" void kernel_launch(void* const* d_in, const int* in_sizes, int n_in,
                              void* d_out, int out_size) {
    (void)in_sizes; (void)n_in; (void)out_size;
    const float* x      = (const float*)d_in[0];
    const float* D      = (const float*)d_in[1];
    const float* n1g    = (const float*)d_in[2];
    const float* n1b    = (const float*)d_in[3];
    const float* qkv_w  = (const float*)d_in[4];
    const float* qkv_b  = (const float*)d_in[5];
    const float* proj_w = (const float*)d_in[6];
    const float* proj_b = (const float*)d_in[7];
    const float* a_p    = (const float*)d_in[8];
    const float* b_p    = (const float*)d_in[9];
    const float* a_r    = (const float*)d_in[10];
    const float* b_r    = (const float*)d_in[11];
    const float* n2g    = (const float*)d_in[12];
    const float* n2b    = (const float*)d_in[13];
    const float* fc1_w  = (const float*)d_in[14];
    const float* fc1_b  = (const float*)d_in[15];
    const float* fc2_w  = (const float*)d_in[16];
    const float* fc2_b  = (const float*)d_in[17];
    float* out = (float*)d_out;

    __half *xw, *qkvh, *at, *xm, *hb, *wq, *wp, *w1, *w2;
    float *x2;
    cudaGetSymbolAddress((void**)&xw, g_xw);
    cudaGetSymbolAddress((void**)&qkvh, g_qkvh);
    cudaGetSymbolAddress((void**)&at, g_at);
    cudaGetSymbolAddress((void**)&xm, g_xm);
    cudaGetSymbolAddress((void**)&hb, g_h);
    cudaGetSymbolAddress((void**)&wq, g_wq);
    cudaGetSymbolAddress((void**)&wp, g_wp);
    cudaGetSymbolAddress((void**)&w1, g_w1);
    cudaGetSymbolAddress((void**)&w2, g_w2);
    cudaGetSymbolAddress((void**)&x2, g_x2);

    cudaFuncSetAttribute(tgemm<EP_BIAS>, cudaFuncAttributeMaxDynamicSharedMemorySize, SMEM_TOT);
    cudaFuncSetAttribute(tgemm<EP_GELU>, cudaFuncAttributeMaxDynamicSharedMemorySize, SMEM_TOT);
    cudaFuncSetAttribute(tgemm<EP_PROJ>, cudaFuncAttributeMaxDynamicSharedMemorySize, SMEM_TOT);
    cudaFuncSetAttribute(tgemm<EP_ADD>,  cudaFuncAttributeMaxDynamicSharedMemorySize, SMEM_TOT);

    // weight conversions into packed layout
    cvt_w<<<(1536 * 512 / 8) / 256, 256>>>(qkv_w,  wq, 1536, 512);
    cvt_w<<<(512 * 512 / 8)  / 256, 256>>>(proj_w, wp, 512,  512);
    cvt_w<<<(2048 * 512 / 8) / 256, 256>>>(fc1_w,  w1, 2048, 512);
    cvt_w<<<(512 * 2048 / 8) / 256, 256>>>(fc2_w,  w2, 512,  2048);

    // 1) LN1 + window partition -> packed fp16
    ln_kernel<<<Mrows / 8, 256>>>(x, n1g, n1b, xw, 1);
    // 2) QKV GEMM -> fp16 natural
    tgemm<EP_BIAS><<<dim3(1536 / 256, Mrows / 128), 256, SMEM_TOT>>>(
        512, 1536, xw, wq, qkv_b, nullptr, nullptr, qkvh);
    // 3) fused windowed attention -> packed fp16
    attn_kernel<<<dim3(1024, 16), 256>>>(qkvh, D, a_p, b_p, a_r, b_r, at);
    // 4) proj GEMM + window reverse + residual
    tgemm<EP_PROJ><<<dim3(512 / 256, Mrows / 128), 256, SMEM_TOT>>>(
        512, 512, at, wp, proj_b, x, x2, nullptr);
    // 5) LN2 -> packed fp16
    ln_kernel<<<Mrows / 8, 256>>>(x2, n2g, n2b, xm, 0);
    // 6) fc1 + GELU -> packed fp16
    tgemm<EP_GELU><<<dim3(2048 / 256, Mrows / 128), 256, SMEM_TOT>>>(
        512, 2048, xm, w1, fc1_b, nullptr, nullptr, hb);
    // 7) fc2 + residual -> output
    tgemm<EP_ADD><<<dim3(512 / 256, Mrows / 128), 256, SMEM_TOT>>>(
        2048, 512, hb, w2, fc2_b, x2, out, nullptr);
}